// round 1
// baseline (speedup 1.0000x reference)
#include <cuda_runtime.h>
#include <cstdint>

#define NH 16
#define SL 2048
#define NB 2
#define HD 64
#define DM 1024
#define BL 4096          // NB*SL
#define NBUCK 32
#define LUTN 4095
#define OUT0 ((size_t)4194304)   // offset of bias region in d_out

typedef unsigned long long ull;

__device__ float g_q[NB*NH*SL*HD];
__device__ float g_k[NB*NH*SL*HD];
__device__ float g_v[NB*NH*SL*HD];
__device__ float g_att[(size_t)BL*DM];
__device__ float g_biasrow[NH*LUTN];

// ---------- packed f32x2 helpers ----------
__device__ __forceinline__ ull pk(float x, float y){
    ull r; asm("mov.b64 %0, {%1, %2};" : "=l"(r) : "f"(x), "f"(y)); return r;
}
__device__ __forceinline__ float2 upk(ull a){
    float2 r; asm("mov.b64 {%0, %1}, %2;" : "=f"(r.x), "=f"(r.y) : "l"(a)); return r;
}
__device__ __forceinline__ ull fma2(ull a, ull b, ull c){
    ull d; asm("fma.rn.f32x2 %0, %1, %2, %3;" : "=l"(d) : "l"(a), "l"(b), "l"(c)); return d;
}
__device__ __forceinline__ ull mul2(ull a, ull b){
    ull d; asm("mul.rn.f32x2 %0, %1, %2;" : "=l"(d) : "l"(a), "l"(b)); return d;
}

// ---------- bias row LUT: bucket(d) exact integer thresholds ----------
__global__ void biasrow_kernel(const float* __restrict__ rel_bias){
    int idx = blockIdx.x*blockDim.x + threadIdx.x;
    if (idx >= NH*LUTN) return;
    int h = idx / LUTN;
    int d = idx % LUTN - 2047;        // d = j - i
    int a = d < 0 ? -d : d;
    int base;
    if (a < 8) base = a;
    else base = 8 + (a>=12) + (a>=16) + (a>=23) + (a>=32) + (a>=46) + (a>=64) + (a>=91);
    int bucket = base + (d > 0 ? 16 : 0);
    g_biasrow[idx] = rel_bias[h*NBUCK + bucket];
}

// ---------- bias output: sliding-window copy of g_biasrow ----------
__global__ void bias_out_kernel(float* __restrict__ out){
    int i = blockIdx.x;               // query row
    int h = blockIdx.y;
    const float* br = g_biasrow + h*LUTN + (2047 - i);
    float* dst = out + ((size_t)h*SL + i)*SL;
    for (int j = threadIdx.x*4; j < SL; j += blockDim.x*4){
        float4 w;
        w.x = br[j]; w.y = br[j+1]; w.z = br[j+2]; w.w = br[j+3];
        *(float4*)(dst + j) = w;
    }
}

// ---------- element writer per GEMM mode ----------
template<int MODE>
__device__ __forceinline__ void put_elem(int r, int c, float v, float* out){
    if (MODE == 0){                   // q projection, pre-scale by 1/sqrt(64)
        int b = r >> 11, l = r & 2047, h = c >> 6, d = c & 63;
        g_q[(((size_t)(b*NH + h))*SL + l)*HD + d] = v * 0.125f;
    } else if (MODE == 1){            // kv projection
        int b = r >> 11, l = r & 2047;
        if (c < DM){
            int h = c >> 6, d = c & 63;
            g_k[(((size_t)(b*NH + h))*SL + l)*HD + d] = v;
        } else {
            int cc = c - DM; int h = cc >> 6, d = cc & 63;
            g_v[(((size_t)(b*NH + h))*SL + l)*HD + d] = v;
        }
    } else {                          // output projection -> d_out [BL, DM]
        out[(size_t)r*DM + c] = v;
    }
}

// ---------- 128x128x8 fp32 GEMM, f32x2 packed FMAs. M=4096, K=1024 fixed ----------
template<int MODE>
__global__ __launch_bounds__(256)
void gemm_kernel(const float* __restrict__ A, const float* __restrict__ W,
                 float* __restrict__ out, int N){
    __shared__ __align__(16) float As[8][132];   // transposed A tile, padded
    __shared__ __align__(16) float Bs[8][128];
    const float* Ap = (MODE == 2) ? (const float*)g_att : A;

    int tid = threadIdx.x;
    int tx = tid & 15, ty = tid >> 4;
    int row0 = blockIdx.y * 128, col0 = blockIdx.x * 128;

    int ar = tid >> 1, ac4 = (tid & 1) * 4;      // A loader
    int bk = tid >> 5, bn4 = (tid & 31) * 4;     // B loader
    const float* aglob = Ap + (size_t)(row0 + ar)*DM + ac4;
    const float* bglob = W + (size_t)bk*N + col0 + bn4;

    ull acc[4][8];
    #pragma unroll
    for (int i = 0; i < 4; i++)
        #pragma unroll
        for (int j = 0; j < 8; j++) acc[i][j] = 0ULL;

    for (int kk = 0; kk < DM; kk += 8){
        float4 av = *(const float4*)aglob; aglob += 8;
        float4 bv = *(const float4*)bglob; bglob += (size_t)8*N;
        __syncthreads();
        As[ac4+0][ar] = av.x; As[ac4+1][ar] = av.y;
        As[ac4+2][ar] = av.z; As[ac4+3][ar] = av.w;
        *(float4*)&Bs[bk][bn4] = bv;
        __syncthreads();
        #pragma unroll
        for (int k = 0; k < 8; k++){
            const ull* apr = (const ull*)&As[k][ty*8];
            ull a0 = apr[0], a1 = apr[1], a2 = apr[2], a3 = apr[3];
            const float4* bpr = (const float4*)&Bs[k][tx*8];
            float4 b0 = bpr[0], b1 = bpr[1];
            ull bb[8];
            bb[0] = pk(b0.x,b0.x); bb[1] = pk(b0.y,b0.y);
            bb[2] = pk(b0.z,b0.z); bb[3] = pk(b0.w,b0.w);
            bb[4] = pk(b1.x,b1.x); bb[5] = pk(b1.y,b1.y);
            bb[6] = pk(b1.z,b1.z); bb[7] = pk(b1.w,b1.w);
            #pragma unroll
            for (int j = 0; j < 8; j++){
                acc[0][j] = fma2(a0, bb[j], acc[0][j]);
                acc[1][j] = fma2(a1, bb[j], acc[1][j]);
                acc[2][j] = fma2(a2, bb[j], acc[2][j]);
                acc[3][j] = fma2(a3, bb[j], acc[3][j]);
            }
        }
    }
    #pragma unroll
    for (int i2 = 0; i2 < 4; i2++)
        #pragma unroll
        for (int j = 0; j < 8; j++){
            float2 v = upk(acc[i2][j]);
            int r = row0 + ty*8 + i2*2;
            int c = col0 + tx*8 + j;
            put_elem<MODE>(r,   c, v.x, out);
            put_elem<MODE>(r+1, c, v.y, out);
        }
}

// ---------- flash attention: 1 q-row/thread, bias via shared LUT ----------
__global__ __launch_bounds__(128)
void attn_kernel(){
    __shared__ __align__(16) float sh_k[64*64];
    __shared__ __align__(16) float sh_v[64*64];
    __shared__ __align__(16) float sh_bias[4096];

    int t = threadIdx.x;
    int h = blockIdx.y, b = blockIdx.z;
    int i = blockIdx.x*128 + t;
    size_t bh = ((size_t)(b*NH + h))*SL*HD;

    // q row -> registers (pre-scaled by 0.125 at projection)
    ull q2[32];
    const ull* qp = (const ull*)(g_q + bh + (size_t)i*HD);
    #pragma unroll
    for (int x = 0; x < 32; x++) q2[x] = qp[x];

    for (int x = t; x < LUTN; x += 128) sh_bias[x] = g_biasrow[h*LUTN + x];

    ull o2[32];
    #pragma unroll
    for (int x = 0; x < 32; x++) o2[x] = 0ULL;
    float m = -1e30f, lsum = 0.f;
    int bidx_base = 2047 - i;

    for (int kt = 0; kt < 32; kt++){
        int j0 = kt << 6;
        __syncthreads();
        {
            const float4* kg = (const float4*)(g_k + bh + (size_t)j0*HD);
            const float4* vg = (const float4*)(g_v + bh + (size_t)j0*HD);
            float4* ks = (float4*)sh_k; float4* vs = (float4*)sh_v;
            #pragma unroll
            for (int x = 0; x < 8; x++){
                ks[x*128 + t] = kg[x*128 + t];
                vs[x*128 + t] = vg[x*128 + t];
            }
        }
        __syncthreads();

        #pragma unroll
        for (int c32 = 0; c32 < 2; c32++){
            float s[32]; float mloc = -1e30f;
            #pragma unroll
            for (int jj = 0; jj < 32; jj++){
                int j = c32*32 + jj;
                const ulonglong2* kr = (const ulonglong2*)(sh_k + (j << 6));
                ull sa = 0ULL, sb = 0ULL;
                #pragma unroll
                for (int x = 0; x < 16; x++){
                    ulonglong2 kv = kr[x];
                    sa = fma2(q2[2*x],   kv.x, sa);
                    sb = fma2(q2[2*x+1], kv.y, sb);
                }
                float2 fa = upk(sa), fb = upk(sb);
                float sv = (fa.x + fa.y) + (fb.x + fb.y) + sh_bias[bidx_base + j0 + j];
                s[jj] = sv;
                mloc = fmaxf(mloc, sv);
            }
            float mnew = fmaxf(m, mloc);
            float corr = __expf(m - mnew);
            lsum *= corr;
            ull c2 = pk(corr, corr);
            #pragma unroll
            for (int x = 0; x < 32; x++) o2[x] = mul2(o2[x], c2);
            #pragma unroll
            for (int jj = 0; jj < 32; jj++){
                float p = __expf(s[jj] - mnew);
                lsum += p;
                ull p2 = pk(p, p);
                const ulonglong2* vr = (const ulonglong2*)(sh_v + ((c32*32 + jj) << 6));
                #pragma unroll
                for (int x = 0; x < 16; x++){
                    ulonglong2 vv = vr[x];
                    o2[2*x]   = fma2(p2, vv.x, o2[2*x]);
                    o2[2*x+1] = fma2(p2, vv.y, o2[2*x+1]);
                }
            }
            m = mnew;
        }
    }
    float rcp = 1.0f / lsum;
    float2* dst = (float2*)(g_att + ((size_t)(b*SL + i))*DM + (h << 6));
    #pragma unroll
    for (int x = 0; x < 32; x++){
        float2 tt = upk(o2[x]);
        tt.x *= rcp; tt.y *= rcp;
        dst[x] = tt;
    }
}

extern "C" void kernel_launch(void* const* d_in, const int* in_sizes, int n_in,
                              void* d_out, int out_size){
    const float* query    = (const float*)d_in[0];
    const float* Wq       = (const float*)d_in[1];
    const float* Wkv      = (const float*)d_in[2];
    const float* Wo       = (const float*)d_in[3];
    const float* rel_bias = (const float*)d_in[4];
    float* out = (float*)d_out;

    biasrow_kernel<<<(NH*LUTN + 255)/256, 256>>>(rel_bias);
    bias_out_kernel<<<dim3(SL, NH), 256>>>(out + OUT0);
    gemm_kernel<0><<<dim3(DM/128,  BL/128), 256>>>(query, Wq,  nullptr, DM);
    gemm_kernel<1><<<dim3(2*DM/128, BL/128), 256>>>(query, Wkv, nullptr, 2*DM);
    attn_kernel<<<dim3(SL/128, NH, NB), 128>>>();
    gemm_kernel<2><<<dim3(DM/128,  BL/128), 256>>>(nullptr, Wo, out, DM);
}

// round 7
// speedup vs baseline: 1.3079x; 1.3079x over previous
#include <cuda_runtime.h>
#include <cuda_bf16.h>
#include <cstdint>

#define NH 16
#define SL 2048
#define NB 2
#define HD 64
#define DM 1024
#define BL 4096          // NB*SL
#define NBUCK 32
#define LUTN 4095
#define OUT0 ((size_t)4194304)   // offset of bias region in d_out

typedef unsigned long long ull;

__device__ float g_q[NB*NH*SL*HD];
__device__ float g_k[NB*NH*SL*HD];
__device__ float g_v[NB*NH*SL*HD];
__device__ float g_att[(size_t)BL*DM];
__device__ float g_biasrow[NH*LUTN];

// bf16 split buffers: A (query, later attn output) and transposed weights
__device__ __nv_bfloat16 g_ah[(size_t)BL*DM];
__device__ __nv_bfloat16 g_al[(size_t)BL*DM];
__device__ __nv_bfloat16 g_wh[(size_t)4*DM*DM];   // Wq^T | Wkv^T | Wo^T, each [N][K]
__device__ __nv_bfloat16 g_wl[(size_t)4*DM*DM];

// ---------- packed f32x2 helpers ----------
__device__ __forceinline__ ull pk(float x, float y){
    ull r; asm("mov.b64 %0, {%1, %2};" : "=l"(r) : "f"(x), "f"(y)); return r;
}
__device__ __forceinline__ float2 upk(ull a){
    float2 r; asm("mov.b64 {%0, %1}, %2;" : "=f"(r.x), "=f"(r.y) : "l"(a)); return r;
}
__device__ __forceinline__ ull fma2(ull a, ull b, ull c){
    ull d; asm("fma.rn.f32x2 %0, %1, %2, %3;" : "=l"(d) : "l"(a), "l"(b), "l"(c)); return d;
}
__device__ __forceinline__ ull mul2(ull a, ull b){
    ull d; asm("mul.rn.f32x2 %0, %1, %2;" : "=l"(d) : "l"(a), "l"(b)); return d;
}

__device__ __forceinline__ uint32_t smem_to_u32(const void* p){
    uint32_t a; asm("{ .reg .u64 t; cvta.to.shared.u64 t, %1; cvt.u32.u64 %0, t; }" : "=r"(a) : "l"(p));
    return a;
}

// ---------- mma.sync / ldmatrix (base ISA, compiles at sm_103) ----------
__device__ __forceinline__ void ldsm4(uint32_t* r, uint32_t addr){
    asm volatile("ldmatrix.sync.aligned.m8n8.x4.shared.b16 {%0,%1,%2,%3}, [%4];"
        : "=r"(r[0]), "=r"(r[1]), "=r"(r[2]), "=r"(r[3]) : "r"(addr));
}
__device__ __forceinline__ void mma16816(float* d, const uint32_t* a, const uint32_t* b){
    asm volatile(
        "mma.sync.aligned.m16n8k16.row.col.f32.bf16.bf16.f32 "
        "{%0,%1,%2,%3}, {%4,%5,%6,%7}, {%8,%9}, {%0,%1,%2,%3};"
        : "+f"(d[0]), "+f"(d[1]), "+f"(d[2]), "+f"(d[3])
        : "r"(a[0]), "r"(a[1]), "r"(a[2]), "r"(a[3]), "r"(b[0]), "r"(b[1]));
}
// swizzled offset within a tile of 64B rows (4 x 16B units); consistent store/load
__device__ __forceinline__ int swz(int r, int u){
    return r*64 + ((u ^ ((r>>1)&3))<<4);
}

// ---------- bias row LUT ----------
__global__ void biasrow_kernel(const float* __restrict__ rel_bias){
    int idx = blockIdx.x*blockDim.x + threadIdx.x;
    if (idx >= NH*LUTN) return;
    int h = idx / LUTN;
    int d = idx % LUTN - 2047;
    int a = d < 0 ? -d : d;
    int base;
    if (a < 8) base = a;
    else base = 8 + (a>=12) + (a>=16) + (a>=23) + (a>=32) + (a>=46) + (a>=64) + (a>=91);
    int bucket = base + (d > 0 ? 16 : 0);
    g_biasrow[idx] = rel_bias[h*NBUCK + bucket];
}

// ---------- bias output ----------
__global__ void bias_out_kernel(float* __restrict__ out){
    int i = blockIdx.x, h = blockIdx.y;
    const float* br = g_biasrow + h*LUTN + (2047 - i);
    float* dst = out + ((size_t)h*SL + i)*SL;
    for (int j = threadIdx.x*4; j < SL; j += blockDim.x*4){
        float4 w; w.x = br[j]; w.y = br[j+1]; w.z = br[j+2]; w.w = br[j+3];
        *(float4*)(dst + j) = w;
    }
}

// ---------- fp32 -> bf16 hi/lo split of activation matrix [BL, DM] ----------
// SRC=0: read from param pointer (query). SRC=1: read g_att (device symbol, device-side).
template<int SRC>
__global__ void conva_kernel(const float* __restrict__ in){
    const float* src = (SRC == 1) ? (const float*)g_att : in;
    int i = blockIdx.x*blockDim.x + threadIdx.x;   // float4 index
    float4 x = ((const float4*)src)[i];
    __nv_bfloat16 h0 = __float2bfloat16(x.x), h1 = __float2bfloat16(x.y);
    __nv_bfloat16 h2 = __float2bfloat16(x.z), h3 = __float2bfloat16(x.w);
    __nv_bfloat16 l0 = __float2bfloat16(x.x - __bfloat162float(h0));
    __nv_bfloat16 l1 = __float2bfloat16(x.y - __bfloat162float(h1));
    __nv_bfloat16 l2 = __float2bfloat16(x.z - __bfloat162float(h2));
    __nv_bfloat16 l3 = __float2bfloat16(x.w - __bfloat162float(h3));
    __nv_bfloat162* ph2 = (__nv_bfloat162*)g_ah;
    __nv_bfloat162* pl2 = (__nv_bfloat162*)g_al;
    ph2[2*i]   = __nv_bfloat162(h0, h1);
    ph2[2*i+1] = __nv_bfloat162(h2, h3);
    pl2[2*i]   = __nv_bfloat162(l0, l1);
    pl2[2*i+1] = __nv_bfloat162(l2, l3);
}

// ---------- transpose + split weights: W[K=1024][N] -> g_wh/g_wl[obase + n*DM + k] ----------
// obase passed as element offset (plain integer; device symbols referenced device-side only)
__global__ void convw_kernel(const float* __restrict__ W, int N, size_t obase){
    __shared__ float tile[32][33];
    int n0 = blockIdx.x*32, k0 = blockIdx.y*32;
    int tx = threadIdx.x;
    for (int r = threadIdx.y; r < 32; r += 8)
        tile[r][tx] = W[(size_t)(k0+r)*N + n0 + tx];
    __syncthreads();
    for (int r = threadIdx.y; r < 32; r += 8){
        float x = tile[tx][r];                 // = W[k0+tx][n0+r]
        __nv_bfloat16 h = __float2bfloat16(x);
        __nv_bfloat16 l = __float2bfloat16(x - __bfloat162float(h));
        size_t o = obase + (size_t)(n0 + r)*DM + k0 + tx;
        g_wh[o] = h; g_wl[o] = l;
    }
}

// ---------- element writer per GEMM mode ----------
template<int MODE>
__device__ __forceinline__ void put_elem(int r, int c, float v, float* out){
    if (MODE == 0){
        int b = r >> 11, l = r & 2047, h = c >> 6, d = c & 63;
        g_q[(((size_t)(b*NH + h))*SL + l)*HD + d] = v * 0.125f;
    } else if (MODE == 1){
        int b = r >> 11, l = r & 2047;
        if (c < DM){
            int h = c >> 6, d = c & 63;
            g_k[(((size_t)(b*NH + h))*SL + l)*HD + d] = v;
        } else {
            int cc = c - DM; int h = cc >> 6, d = cc & 63;
            g_v[(((size_t)(b*NH + h))*SL + l)*HD + d] = v;
        }
    } else {
        out[(size_t)r*DM + c] = v;
    }
}

// ---------- bf16-split mma.sync GEMM: C[4096, N] = A[4096,1024] @ Wt^T ----------
// CTA tile 128(m) x 64(n), K-chunk 32. 8 warps: 2(m) x 4(n), warp tile 64x16.
// Static SMEM 48KB: 2 stages x [Ah 8K | Al 8K | Bh 4K | Bl 4K], 64B rows, XOR-swizzled.
// Weight base chosen by MODE (device-side symbol arithmetic only).
template<int MODE>
__global__ __launch_bounds__(256)
void tgemm_kernel(float* __restrict__ out){
    __shared__ __align__(128) char smem[49152];
    int tid = threadIdx.x, lane = tid & 31, wid = tid >> 5;
    int wm = wid & 1, wn = wid >> 1;
    int row0 = blockIdx.y * 128, col0 = blockIdx.x * 64;

    const size_t WOFF = (MODE == 0) ? 0 : (MODE == 1) ? (size_t)DM*DM : (size_t)3*DM*DM;
    const __nv_bfloat16* Asrc_h = g_ah + (size_t)row0*DM;
    const __nv_bfloat16* Asrc_l = g_al + (size_t)row0*DM;
    const __nv_bfloat16* Bsrc_h = g_wh + WOFF + (size_t)col0*DM;
    const __nv_bfloat16* Bsrc_l = g_wl + WOFF + (size_t)col0*DM;

    int lr = tid >> 2, lu = tid & 3;   // loader coords: row, 16B-unit

    uint4 v[6];
    auto ldg_chunk = [&](int kc){
        size_t off = (size_t)lr*DM + kc*32 + lu*8;
        v[0] = *(const uint4*)(Asrc_h + off);
        v[1] = *(const uint4*)(Asrc_h + off + (size_t)64*DM);
        v[2] = *(const uint4*)(Asrc_l + off);
        v[3] = *(const uint4*)(Asrc_l + off + (size_t)64*DM);
        v[4] = *(const uint4*)(Bsrc_h + off);
        v[5] = *(const uint4*)(Bsrc_l + off);
    };
    auto sts_chunk = [&](int s){
        char* st = smem + s*24576;
        *(uint4*)(st +         swz(lr,    lu)) = v[0];
        *(uint4*)(st +         swz(lr+64, lu)) = v[1];
        *(uint4*)(st +  8192 + swz(lr,    lu)) = v[2];
        *(uint4*)(st +  8192 + swz(lr+64, lu)) = v[3];
        *(uint4*)(st + 16384 + swz(lr,    lu)) = v[4];
        *(uint4*)(st + 20480 + swz(lr,    lu)) = v[5];
    };

    uint32_t sbase = smem_to_u32(smem);
    int mat = lane >> 3, rim = lane & 7;

    float acc[4][2][4];
    #pragma unroll
    for (int a = 0; a < 4; a++)
        #pragma unroll
        for (int b = 0; b < 2; b++)
            #pragma unroll
            for (int c = 0; c < 4; c++) acc[a][b][c] = 0.f;

    ldg_chunk(0);
    sts_chunk(0);
    __syncthreads();

    for (int kc = 0; kc < 32; kc++){
        int s = kc & 1;
        if (kc < 31) ldg_chunk(kc + 1);

        uint32_t sa_h = sbase + s*24576;
        uint32_t sa_l = sa_h + 8192;
        uint32_t sb_h = sa_h + 16384;
        uint32_t sb_l = sa_h + 20480;

        #pragma unroll
        for (int kk = 0; kk < 2; kk++){
            int un = 2*kk + (mat >> 1);
            int br = wn*16 + (mat & 1)*8 + rim;
            uint32_t tb[4], bh[2][2], bl[2][2];
            ldsm4(tb, sb_h + swz(br, un));
            bh[0][0]=tb[0]; bh[0][1]=tb[2]; bh[1][0]=tb[1]; bh[1][1]=tb[3];
            ldsm4(tb, sb_l + swz(br, un));
            bl[0][0]=tb[0]; bl[0][1]=tb[2]; bl[1][0]=tb[1]; bl[1][1]=tb[3];
            #pragma unroll
            for (int mt = 0; mt < 4; mt++){
                int ar = wm*64 + mt*16 + (mat & 1)*8 + rim;
                uint32_t ah[4], al[4];
                ldsm4(ah, sa_h + swz(ar, un));
                ldsm4(al, sa_l + swz(ar, un));
                #pragma unroll
                for (int nf = 0; nf < 2; nf++){
                    mma16816(acc[mt][nf], ah, bh[nf]);
                    mma16816(acc[mt][nf], ah, bl[nf]);
                    mma16816(acc[mt][nf], al, bh[nf]);
                }
            }
        }
        if (kc < 31){
            sts_chunk(s ^ 1);
            __syncthreads();
        }
    }

    // epilogue: D frag -> thread (m = l/4 [+8], n = 2*(l%4) [+1])
    #pragma unroll
    for (int mt = 0; mt < 4; mt++)
        #pragma unroll
        for (int nf = 0; nf < 2; nf++){
            int m = row0 + wm*64 + mt*16 + (lane >> 2);
            int c = col0 + wn*16 + nf*8 + 2*(lane & 3);
            put_elem<MODE>(m,     c,     acc[mt][nf][0], out);
            put_elem<MODE>(m,     c + 1, acc[mt][nf][1], out);
            put_elem<MODE>(m + 8, c,     acc[mt][nf][2], out);
            put_elem<MODE>(m + 8, c + 1, acc[mt][nf][3], out);
        }
}

// ---------- flash attention: 1 q-row/thread, bias via shared LUT ----------
__global__ __launch_bounds__(128)
void attn_kernel(){
    __shared__ __align__(16) float sh_k[64*64];
    __shared__ __align__(16) float sh_v[64*64];
    __shared__ __align__(16) float sh_bias[4096];

    int t = threadIdx.x;
    int h = blockIdx.y, b = blockIdx.z;
    int i = blockIdx.x*128 + t;
    size_t bh = ((size_t)(b*NH + h))*SL*HD;

    ull q2[32];
    const ull* qp = (const ull*)(g_q + bh + (size_t)i*HD);
    #pragma unroll
    for (int x = 0; x < 32; x++) q2[x] = qp[x];

    for (int x = t; x < LUTN; x += 128) sh_bias[x] = g_biasrow[h*LUTN + x];

    ull o2[32];
    #pragma unroll
    for (int x = 0; x < 32; x++) o2[x] = 0ULL;
    float m = -1e30f, lsum = 0.f;
    int bidx_base = 2047 - i;

    for (int kt = 0; kt < 32; kt++){
        int j0 = kt << 6;
        __syncthreads();
        {
            const float4* kg = (const float4*)(g_k + bh + (size_t)j0*HD);
            const float4* vg = (const float4*)(g_v + bh + (size_t)j0*HD);
            float4* ks = (float4*)sh_k; float4* vs = (float4*)sh_v;
            #pragma unroll
            for (int x = 0; x < 8; x++){
                ks[x*128 + t] = kg[x*128 + t];
                vs[x*128 + t] = vg[x*128 + t];
            }
        }
        __syncthreads();

        #pragma unroll
        for (int c32 = 0; c32 < 2; c32++){
            float s[32]; float mloc = -1e30f;
            #pragma unroll
            for (int jj = 0; jj < 32; jj++){
                int j = c32*32 + jj;
                const ulonglong2* kr = (const ulonglong2*)(sh_k + (j << 6));
                ull sa = 0ULL, sb2 = 0ULL;
                #pragma unroll
                for (int x = 0; x < 16; x++){
                    ulonglong2 kv = kr[x];
                    sa  = fma2(q2[2*x],   kv.x, sa);
                    sb2 = fma2(q2[2*x+1], kv.y, sb2);
                }
                float2 fa = upk(sa), fb = upk(sb2);
                float sv = (fa.x + fa.y) + (fb.x + fb.y) + sh_bias[bidx_base + j0 + j];
                s[jj] = sv;
                mloc = fmaxf(mloc, sv);
            }
            float mnew = fmaxf(m, mloc);
            float corr = __expf(m - mnew);
            lsum *= corr;
            ull c2 = pk(corr, corr);
            #pragma unroll
            for (int x = 0; x < 32; x++) o2[x] = mul2(o2[x], c2);
            #pragma unroll
            for (int jj = 0; jj < 32; jj++){
                float p = __expf(s[jj] - mnew);
                lsum += p;
                ull p2 = pk(p, p);
                const ulonglong2* vr = (const ulonglong2*)(sh_v + ((c32*32 + jj) << 6));
                #pragma unroll
                for (int x = 0; x < 16; x++){
                    ulonglong2 vv = vr[x];
                    o2[2*x]   = fma2(p2, vv.x, o2[2*x]);
                    o2[2*x+1] = fma2(p2, vv.y, o2[2*x+1]);
                }
            }
            m = mnew;
        }
    }
    float rcp = 1.0f / lsum;
    float2* dst = (float2*)(g_att + ((size_t)(b*SL + i))*DM + (h << 6));
    #pragma unroll
    for (int x = 0; x < 32; x++){
        float2 tt = upk(o2[x]);
        tt.x *= rcp; tt.y *= rcp;
        dst[x] = tt;
    }
}

extern "C" void kernel_launch(void* const* d_in, const int* in_sizes, int n_in,
                              void* d_out, int out_size){
    const float* query    = (const float*)d_in[0];
    const float* Wq       = (const float*)d_in[1];
    const float* Wkv      = (const float*)d_in[2];
    const float* Wo       = (const float*)d_in[3];
    const float* rel_bias = (const float*)d_in[4];
    float* out = (float*)d_out;

    biasrow_kernel<<<(NH*LUTN + 255)/256, 256>>>(rel_bias);
    bias_out_kernel<<<dim3(SL, NH), 256>>>(out + OUT0);

    // weight transpose + bf16 split (slot offsets as plain integers)
    convw_kernel<<<dim3(DM/32, DM/32),   dim3(32,8)>>>(Wq,  DM,   (size_t)0);
    convw_kernel<<<dim3(2*DM/32, DM/32), dim3(32,8)>>>(Wkv, 2*DM, (size_t)DM*DM);
    convw_kernel<<<dim3(DM/32, DM/32),   dim3(32,8)>>>(Wo,  DM,   (size_t)3*DM*DM);

    // query -> bf16 split
    conva_kernel<0><<<BL*DM/4/256, 256>>>(query);

    tgemm_kernel<0><<<dim3(DM/64,   BL/128), 256>>>(nullptr);
    tgemm_kernel<1><<<dim3(2*DM/64, BL/128), 256>>>(nullptr);

    attn_kernel<<<dim3(SL/128, NH, NB), 128>>>();

    // attn output -> bf16 split (read g_att device-side), then Wo projection
    conva_kernel<1><<<BL*DM/4/256, 256>>>(nullptr);
    tgemm_kernel<2><<<dim3(DM/64,   BL/128), 256>>>(out);
}

// round 10
// speedup vs baseline: 2.2121x; 1.6914x over previous
#include <cuda_runtime.h>
#include <cuda_bf16.h>
#include <cstdint>

#define NH 16
#define SL 2048
#define NB 2
#define HD 64
#define DM 1024
#define BL 4096          // NB*SL
#define NBUCK 32
#define LUTN 4095
#define OUT0 ((size_t)4194304)   // offset of bias region in d_out

__device__ float g_biasrow[NH*LUTN];

// bf16 split buffers
__device__ __nv_bfloat16 g_ah[(size_t)BL*DM];   // activations (query, then attn out)
__device__ __nv_bfloat16 g_al[(size_t)BL*DM];
__device__ __nv_bfloat16 g_wh[(size_t)4*DM*DM]; // Wq^T | Wkv^T | Wo^T, each [N][K]
__device__ __nv_bfloat16 g_wl[(size_t)4*DM*DM];
__device__ __nv_bfloat16 g_qh[(size_t)NB*NH*SL*HD];  // [b,h,q,d], pre-scaled 0.125
__device__ __nv_bfloat16 g_ql[(size_t)NB*NH*SL*HD];
__device__ __nv_bfloat16 g_kh[(size_t)NB*NH*SL*HD];  // [b,h,key,d]
__device__ __nv_bfloat16 g_kl[(size_t)NB*NH*SL*HD];
__device__ __nv_bfloat16 g_vth[(size_t)NB*NH*HD*SL]; // [b,h,d,key]  (transposed)
__device__ __nv_bfloat16 g_vtl[(size_t)NB*NH*HD*SL];

__device__ __forceinline__ uint32_t smem_to_u32(const void* p){
    uint32_t a; asm("{ .reg .u64 t; cvta.to.shared.u64 t, %1; cvt.u32.u64 %0, t; }" : "=r"(a) : "l"(p));
    return a;
}

// ---------- mma.sync / ldmatrix (base ISA) ----------
__device__ __forceinline__ void ldsm4(uint32_t* r, uint32_t addr){
    asm volatile("ldmatrix.sync.aligned.m8n8.x4.shared.b16 {%0,%1,%2,%3}, [%4];"
        : "=r"(r[0]), "=r"(r[1]), "=r"(r[2]), "=r"(r[3]) : "r"(addr));
}
__device__ __forceinline__ void mma16816(float* d, const uint32_t* a, const uint32_t* b){
    asm volatile(
        "mma.sync.aligned.m16n8k16.row.col.f32.bf16.bf16.f32 "
        "{%0,%1,%2,%3}, {%4,%5,%6,%7}, {%8,%9}, {%0,%1,%2,%3};"
        : "+f"(d[0]), "+f"(d[1]), "+f"(d[2]), "+f"(d[3])
        : "r"(a[0]), "r"(a[1]), "r"(a[2]), "r"(a[3]), "r"(b[0]), "r"(b[1]));
}
// swizzle for 64B rows (4x16B units) — tgemm tiles
__device__ __forceinline__ int swz(int r, int u){
    return r*64 + ((u ^ ((r>>1)&3))<<4);
}
// swizzle for 128B rows (8x16B units) — attention K/V tiles
__device__ __forceinline__ int swzK(int r, int u){
    return r*128 + ((u ^ (r&7))<<4);
}
__device__ __forceinline__ uint32_t pack_bf2(float a, float b){
    __nv_bfloat162 t(__float2bfloat16(a), __float2bfloat16(b));
    return *(uint32_t*)&t;
}

// ---------- bias row LUT ----------
__global__ void biasrow_kernel(const float* __restrict__ rel_bias){
    int idx = blockIdx.x*blockDim.x + threadIdx.x;
    if (idx >= NH*LUTN) return;
    int h = idx / LUTN;
    int d = idx % LUTN - 2047;
    int a = d < 0 ? -d : d;
    int base;
    if (a < 8) base = a;
    else base = 8 + (a>=12) + (a>=16) + (a>=23) + (a>=32) + (a>=46) + (a>=64) + (a>=91);
    int bucket = base + (d > 0 ? 16 : 0);
    g_biasrow[idx] = rel_bias[h*NBUCK + bucket];
}

// ---------- bias output ----------
__global__ void bias_out_kernel(float* __restrict__ out){
    int i = blockIdx.x, h = blockIdx.y;
    const float* br = g_biasrow + h*LUTN + (2047 - i);
    float* dst = out + ((size_t)h*SL + i)*SL;
    for (int j = threadIdx.x*4; j < SL; j += blockDim.x*4){
        float4 w; w.x = br[j]; w.y = br[j+1]; w.z = br[j+2]; w.w = br[j+3];
        *(float4*)(dst + j) = w;
    }
}

// ---------- fp32 query -> bf16 hi/lo split [BL, DM] ----------
__global__ void conva_kernel(const float* __restrict__ in){
    int i = blockIdx.x*blockDim.x + threadIdx.x;   // float4 index
    float4 x = ((const float4*)in)[i];
    __nv_bfloat16 h0 = __float2bfloat16(x.x), h1 = __float2bfloat16(x.y);
    __nv_bfloat16 h2 = __float2bfloat16(x.z), h3 = __float2bfloat16(x.w);
    __nv_bfloat16 l0 = __float2bfloat16(x.x - __bfloat162float(h0));
    __nv_bfloat16 l1 = __float2bfloat16(x.y - __bfloat162float(h1));
    __nv_bfloat16 l2 = __float2bfloat16(x.z - __bfloat162float(h2));
    __nv_bfloat16 l3 = __float2bfloat16(x.w - __bfloat162float(h3));
    __nv_bfloat162* ph2 = (__nv_bfloat162*)g_ah;
    __nv_bfloat162* pl2 = (__nv_bfloat162*)g_al;
    ph2[2*i]   = __nv_bfloat162(h0, h1);
    ph2[2*i+1] = __nv_bfloat162(h2, h3);
    pl2[2*i]   = __nv_bfloat162(l0, l1);
    pl2[2*i+1] = __nv_bfloat162(l2, l3);
}

// ---------- transpose + split weights: W[K=1024][N] -> g_wh/g_wl[obase + n*DM + k] ----------
__global__ void convw_kernel(const float* __restrict__ W, int N, size_t obase){
    __shared__ float tile[32][33];
    int n0 = blockIdx.x*32, k0 = blockIdx.y*32;
    int tx = threadIdx.x;
    for (int r = threadIdx.y; r < 32; r += 8)
        tile[r][tx] = W[(size_t)(k0+r)*N + n0 + tx];
    __syncthreads();
    for (int r = threadIdx.y; r < 32; r += 8){
        float x = tile[tx][r];                 // = W[k0+tx][n0+r]
        __nv_bfloat16 h = __float2bfloat16(x);
        __nv_bfloat16 l = __float2bfloat16(x - __bfloat162float(h));
        size_t o = obase + (size_t)(n0 + r)*DM + k0 + tx;
        g_wh[o] = h; g_wl[o] = l;
    }
}

// ---------- element writer per GEMM mode ----------
template<int MODE>
__device__ __forceinline__ void put_elem(int r, int c, float v, float* out){
    if (MODE == 0){                   // q: scale by 0.125, bf16 split, [b,h,q,d]
        int b = r >> 11, l = r & 2047, hh = c >> 6, d = c & 63;
        float x = v * 0.125f;
        __nv_bfloat16 th = __float2bfloat16(x);
        __nv_bfloat16 tl = __float2bfloat16(x - __bfloat162float(th));
        size_t idx = (((size_t)(b*NH + hh))*SL + l)*HD + d;
        g_qh[idx] = th; g_ql[idx] = tl;
    } else if (MODE == 1){            // k: [b,h,key,d] split; v: transposed [b,h,d,key] split
        int b = r >> 11, l = r & 2047;
        __nv_bfloat16 th = __float2bfloat16(v);
        __nv_bfloat16 tl = __float2bfloat16(v - __bfloat162float(th));
        if (c < DM){
            int hh = c >> 6, d = c & 63;
            size_t idx = (((size_t)(b*NH + hh))*SL + l)*HD + d;
            g_kh[idx] = th; g_kl[idx] = tl;
        } else {
            int cc = c - DM; int hh = cc >> 6, d = cc & 63;
            size_t idx = (((size_t)(b*NH + hh))*HD + d)*SL + l;
            g_vth[idx] = th; g_vtl[idx] = tl;
        }
    } else {                          // output projection -> d_out [BL, DM]
        out[(size_t)r*DM + c] = v;
    }
}

// ---------- bf16-split mma.sync GEMM: C[4096, N] = A[4096,1024] @ Wt^T ----------
template<int MODE>
__global__ __launch_bounds__(256)
void tgemm_kernel(float* __restrict__ out){
    __shared__ __align__(128) char smem[49152];
    int tid = threadIdx.x, lane = tid & 31, wid = tid >> 5;
    int wm = wid & 1, wn = wid >> 1;
    int row0 = blockIdx.y * 128, col0 = blockIdx.x * 64;

    const size_t WOFF = (MODE == 0) ? 0 : (MODE == 1) ? (size_t)DM*DM : (size_t)3*DM*DM;
    const __nv_bfloat16* Asrc_h = g_ah + (size_t)row0*DM;
    const __nv_bfloat16* Asrc_l = g_al + (size_t)row0*DM;
    const __nv_bfloat16* Bsrc_h = g_wh + WOFF + (size_t)col0*DM;
    const __nv_bfloat16* Bsrc_l = g_wl + WOFF + (size_t)col0*DM;

    int lr = tid >> 2, lu = tid & 3;   // loader coords: row, 16B-unit

    uint4 v[6];
    auto ldg_chunk = [&](int kc){
        size_t off = (size_t)lr*DM + kc*32 + lu*8;
        v[0] = *(const uint4*)(Asrc_h + off);
        v[1] = *(const uint4*)(Asrc_h + off + (size_t)64*DM);
        v[2] = *(const uint4*)(Asrc_l + off);
        v[3] = *(const uint4*)(Asrc_l + off + (size_t)64*DM);
        v[4] = *(const uint4*)(Bsrc_h + off);
        v[5] = *(const uint4*)(Bsrc_l + off);
    };
    auto sts_chunk = [&](int s){
        char* st = smem + s*24576;
        *(uint4*)(st +         swz(lr,    lu)) = v[0];
        *(uint4*)(st +         swz(lr+64, lu)) = v[1];
        *(uint4*)(st +  8192 + swz(lr,    lu)) = v[2];
        *(uint4*)(st +  8192 + swz(lr+64, lu)) = v[3];
        *(uint4*)(st + 16384 + swz(lr,    lu)) = v[4];
        *(uint4*)(st + 20480 + swz(lr,    lu)) = v[5];
    };

    uint32_t sbase = smem_to_u32(smem);
    int mat = lane >> 3, rim = lane & 7;

    float acc[4][2][4];
    #pragma unroll
    for (int a = 0; a < 4; a++)
        #pragma unroll
        for (int b = 0; b < 2; b++)
            #pragma unroll
            for (int c = 0; c < 4; c++) acc[a][b][c] = 0.f;

    ldg_chunk(0);
    sts_chunk(0);
    __syncthreads();

    #pragma unroll 1
    for (int kc = 0; kc < 32; kc++){
        int s = kc & 1;
        if (kc < 31) ldg_chunk(kc + 1);

        uint32_t sa_h = sbase + s*24576;
        uint32_t sa_l = sa_h + 8192;
        uint32_t sb_h = sa_h + 16384;
        uint32_t sb_l = sa_h + 20480;

        #pragma unroll
        for (int kk = 0; kk < 2; kk++){
            int un = 2*kk + (mat >> 1);
            int br = wn*16 + (mat & 1)*8 + rim;
            uint32_t tb[4], bh[2][2], bl[2][2];
            ldsm4(tb, sb_h + swz(br, un));
            bh[0][0]=tb[0]; bh[0][1]=tb[2]; bh[1][0]=tb[1]; bh[1][1]=tb[3];
            ldsm4(tb, sb_l + swz(br, un));
            bl[0][0]=tb[0]; bl[0][1]=tb[2]; bl[1][0]=tb[1]; bl[1][1]=tb[3];
            #pragma unroll
            for (int mt = 0; mt < 4; mt++){
                int ar = wm*64 + mt*16 + (mat & 1)*8 + rim;
                uint32_t ah[4], al[4];
                ldsm4(ah, sa_h + swz(ar, un));
                ldsm4(al, sa_l + swz(ar, un));
                #pragma unroll
                for (int nf = 0; nf < 2; nf++){
                    mma16816(acc[mt][nf], ah, bh[nf]);
                    mma16816(acc[mt][nf], ah, bl[nf]);
                    mma16816(acc[mt][nf], al, bh[nf]);
                }
            }
        }
        if (kc < 31){
            sts_chunk(s ^ 1);
            __syncthreads();
        }
    }

    #pragma unroll
    for (int mt = 0; mt < 4; mt++)
        #pragma unroll
        for (int nf = 0; nf < 2; nf++){
            int m = row0 + wm*64 + mt*16 + (lane >> 2);
            int c = col0 + wn*16 + nf*8 + 2*(lane & 3);
            put_elem<MODE>(m,     c,     acc[mt][nf][0], out);
            put_elem<MODE>(m,     c + 1, acc[mt][nf][1], out);
            put_elem<MODE>(m + 8, c,     acc[mt][nf][2], out);
            put_elem<MODE>(m + 8, c + 1, acc[mt][nf][3], out);
        }
}

// ---------- flash attention via mma.sync, bf16 3-term split for QK^T and P.V ----------
// 8 warps x 16 q-rows = 128 q-rows per CTA. K-tiles of 64 keys.
// SMEM (static 48KB): Kh@0, Kl@8192, Vth@16384, Vtl@24576 (each 64x128B swizzled), bias@32768 (16KB)
__global__ __launch_bounds__(256)
void attn_kernel(){
    __shared__ __align__(128) char smem[49152];
    float* sh_bias = (float*)(smem + 32768);

    int tid = threadIdx.x, lane = tid & 31, wid = tid >> 5;
    int g = lane >> 2, tig = lane & 3, mat = lane >> 3, rim = lane & 7;
    int h = blockIdx.y, b = blockIdx.z;
    size_t bhoff = ((size_t)(b*NH + h))*SL*HD;
    int qrow0 = blockIdx.x*128 + wid*16;
    int r0 = qrow0 + g;                 // thread's first q-row; second is r0+8

    #pragma unroll 1
    for (int x = tid; x < LUTN; x += 256) sh_bias[x] = g_biasrow[h*LUTN + x];

    // Q fragments (a-frag layout), loaded once from global
    uint32_t qh[4][4], ql[4][4];
    #pragma unroll
    for (int kc = 0; kc < 4; kc++){
        size_t o00 = bhoff + (size_t)r0*HD     + kc*16 + 2*tig;
        size_t o10 = bhoff + (size_t)(r0+8)*HD + kc*16 + 2*tig;
        qh[kc][0] = *(const uint32_t*)(g_qh + o00);
        qh[kc][1] = *(const uint32_t*)(g_qh + o10);
        qh[kc][2] = *(const uint32_t*)(g_qh + o00 + 8);
        qh[kc][3] = *(const uint32_t*)(g_qh + o10 + 8);
        ql[kc][0] = *(const uint32_t*)(g_ql + o00);
        ql[kc][1] = *(const uint32_t*)(g_ql + o10);
        ql[kc][2] = *(const uint32_t*)(g_ql + o00 + 8);
        ql[kc][3] = *(const uint32_t*)(g_ql + o10 + 8);
    }

    float S[8][4], O[8][4];
    #pragma unroll
    for (int nt = 0; nt < 8; nt++)
        #pragma unroll
        for (int vv = 0; vv < 4; vv++) O[nt][vv] = 0.f;
    float m0 = -1e30f, m1 = -1e30f, l0 = 0.f, l1 = 0.f;

    uint32_t sbase = smem_to_u32(smem);
    uint32_t sKh = sbase, sKl = sbase + 8192, sVh = sbase + 16384, sVl = sbase + 24576;
    int ib0 = 2047 - r0;

    #pragma unroll 1
    for (int kt = 0; kt < 32; kt++){
        int j0 = kt << 6;
        __syncthreads();
        #pragma unroll
        for (int i = 0; i < 2; i++){
            int id = tid + 256*i, r = id >> 3, u = id & 7;
            int so = swzK(r, u);
            *(uint4*)(smem + so)         = *(const uint4*)(g_kh  + bhoff + (size_t)(j0+r)*HD + u*8);
            *(uint4*)(smem + 8192 + so)  = *(const uint4*)(g_kl  + bhoff + (size_t)(j0+r)*HD + u*8);
            *(uint4*)(smem + 16384 + so) = *(const uint4*)(g_vth + bhoff + (size_t)r*SL + j0 + u*8);
            *(uint4*)(smem + 24576 + so) = *(const uint4*)(g_vtl + bhoff + (size_t)r*SL + j0 + u*8);
        }
        __syncthreads();

        // ---- S = Q K^T (3-term split) ----
        #pragma unroll
        for (int nt = 0; nt < 8; nt++)
            #pragma unroll
            for (int vv = 0; vv < 4; vv++) S[nt][vv] = 0.f;
        #pragma unroll
        for (int kc = 0; kc < 4; kc++){
            #pragma unroll
            for (int np = 0; np < 4; np++){
                int so = swzK(np*16 + (mat & 1)*8 + rim, 2*kc + (mat >> 1));
                uint32_t tb[4], bh0[2], bh1[2], bl0[2], bl1[2];
                ldsm4(tb, sKh + so);
                bh0[0]=tb[0]; bh0[1]=tb[2]; bh1[0]=tb[1]; bh1[1]=tb[3];
                ldsm4(tb, sKl + so);
                bl0[0]=tb[0]; bl0[1]=tb[2]; bl1[0]=tb[1]; bl1[1]=tb[3];
                mma16816(S[2*np],   qh[kc], bh0);
                mma16816(S[2*np],   qh[kc], bl0);
                mma16816(S[2*np],   ql[kc], bh0);
                mma16816(S[2*np+1], qh[kc], bh1);
                mma16816(S[2*np+1], qh[kc], bl1);
                mma16816(S[2*np+1], ql[kc], bh1);
            }
        }

        // ---- bias + online softmax ----
        float mx0 = -1e30f, mx1 = -1e30f;
        #pragma unroll
        for (int nt = 0; nt < 8; nt++){
            int j = j0 + nt*8 + 2*tig;
            S[nt][0] += sh_bias[ib0 + j];
            S[nt][1] += sh_bias[ib0 + j + 1];
            S[nt][2] += sh_bias[ib0 - 8 + j];
            S[nt][3] += sh_bias[ib0 - 8 + j + 1];
            mx0 = fmaxf(mx0, fmaxf(S[nt][0], S[nt][1]));
            mx1 = fmaxf(mx1, fmaxf(S[nt][2], S[nt][3]));
        }
        mx0 = fmaxf(mx0, __shfl_xor_sync(0xffffffffu, mx0, 1));
        mx0 = fmaxf(mx0, __shfl_xor_sync(0xffffffffu, mx0, 2));
        mx1 = fmaxf(mx1, __shfl_xor_sync(0xffffffffu, mx1, 1));
        mx1 = fmaxf(mx1, __shfl_xor_sync(0xffffffffu, mx1, 2));
        float mn0 = fmaxf(m0, mx0), mn1 = fmaxf(m1, mx1);
        float c0 = __expf(m0 - mn0), c1 = __expf(m1 - mn1);
        float s0 = 0.f, s1 = 0.f;
        #pragma unroll
        for (int nt = 0; nt < 8; nt++){
            S[nt][0] = __expf(S[nt][0] - mn0);
            S[nt][1] = __expf(S[nt][1] - mn0);
            S[nt][2] = __expf(S[nt][2] - mn1);
            S[nt][3] = __expf(S[nt][3] - mn1);
            s0 += S[nt][0] + S[nt][1];
            s1 += S[nt][2] + S[nt][3];
            O[nt][0] *= c0; O[nt][1] *= c0;
            O[nt][2] *= c1; O[nt][3] *= c1;
        }
        s0 += __shfl_xor_sync(0xffffffffu, s0, 1);
        s0 += __shfl_xor_sync(0xffffffffu, s0, 2);
        s1 += __shfl_xor_sync(0xffffffffu, s1, 1);
        s1 += __shfl_xor_sync(0xffffffffu, s1, 2);
        l0 = l0*c0 + s0;  l1 = l1*c1 + s1;
        m0 = mn0;  m1 = mn1;

        // ---- O += P V (3-term split; P a-frags built from S c-frags) ----
        #pragma unroll
        for (int kc2 = 0; kc2 < 4; kc2++){
            int t0 = 2*kc2, t1 = 2*kc2 + 1;
            uint32_t ph[4], pl[4];
            float h00 = __bfloat162float(__float2bfloat16(S[t0][0]));
            float h01 = __bfloat162float(__float2bfloat16(S[t0][1]));
            float h02 = __bfloat162float(__float2bfloat16(S[t0][2]));
            float h03 = __bfloat162float(__float2bfloat16(S[t0][3]));
            float h10 = __bfloat162float(__float2bfloat16(S[t1][0]));
            float h11 = __bfloat162float(__float2bfloat16(S[t1][1]));
            float h12 = __bfloat162float(__float2bfloat16(S[t1][2]));
            float h13 = __bfloat162float(__float2bfloat16(S[t1][3]));
            ph[0] = pack_bf2(h00, h01);
            ph[1] = pack_bf2(h02, h03);
            ph[2] = pack_bf2(h10, h11);
            ph[3] = pack_bf2(h12, h13);
            pl[0] = pack_bf2(S[t0][0] - h00, S[t0][1] - h01);
            pl[1] = pack_bf2(S[t0][2] - h02, S[t0][3] - h03);
            pl[2] = pack_bf2(S[t1][0] - h10, S[t1][1] - h11);
            pl[3] = pack_bf2(S[t1][2] - h12, S[t1][3] - h13);
            #pragma unroll
            for (int np = 0; np < 4; np++){
                int so = swzK(np*16 + (mat & 1)*8 + rim, 2*kc2 + (mat >> 1));
                uint32_t tb[4], vh0[2], vh1[2], vl0[2], vl1[2];
                ldsm4(tb, sVh + so);
                vh0[0]=tb[0]; vh0[1]=tb[2]; vh1[0]=tb[1]; vh1[1]=tb[3];
                ldsm4(tb, sVl + so);
                vl0[0]=tb[0]; vl0[1]=tb[2]; vl1[0]=tb[1]; vl1[1]=tb[3];
                mma16816(O[2*np],   ph, vh0);
                mma16816(O[2*np],   ph, vl0);
                mma16816(O[2*np],   pl, vh0);
                mma16816(O[2*np+1], ph, vh1);
                mma16816(O[2*np+1], ph, vl1);
                mma16816(O[2*np+1], pl, vh1);
            }
        }
    }

    // ---- epilogue: normalize, bf16-split, write g_ah/g_al directly ----
    float rc0 = 1.0f / l0, rc1 = 1.0f / l1;
    size_t rowA = ((size_t)(b*SL + r0))*DM + h*HD;
    size_t rowB = ((size_t)(b*SL + r0 + 8))*DM + h*HD;
    #pragma unroll
    for (int nt = 0; nt < 8; nt++){
        int d = nt*8 + 2*tig;
        float o0 = O[nt][0]*rc0, o1 = O[nt][1]*rc0;
        float o2 = O[nt][2]*rc1, o3 = O[nt][3]*rc1;
        __nv_bfloat16 h0 = __float2bfloat16(o0), h1 = __float2bfloat16(o1);
        __nv_bfloat16 h2 = __float2bfloat16(o2), h3 = __float2bfloat16(o3);
        *(__nv_bfloat162*)(g_ah + rowA + d) = __nv_bfloat162(h0, h1);
        *(__nv_bfloat162*)(g_ah + rowB + d) = __nv_bfloat162(h2, h3);
        *(__nv_bfloat162*)(g_al + rowA + d) = __nv_bfloat162(
            __float2bfloat16(o0 - __bfloat162float(h0)), __float2bfloat16(o1 - __bfloat162float(h1)));
        *(__nv_bfloat162*)(g_al + rowB + d) = __nv_bfloat162(
            __float2bfloat16(o2 - __bfloat162float(h2)), __float2bfloat16(o3 - __bfloat162float(h3)));
    }
}

extern "C" void kernel_launch(void* const* d_in, const int* in_sizes, int n_in,
                              void* d_out, int out_size){
    const float* query    = (const float*)d_in[0];
    const float* Wq       = (const float*)d_in[1];
    const float* Wkv      = (const float*)d_in[2];
    const float* Wo       = (const float*)d_in[3];
    const float* rel_bias = (const float*)d_in[4];
    float* out = (float*)d_out;

    biasrow_kernel<<<(NH*LUTN + 255)/256, 256>>>(rel_bias);
    bias_out_kernel<<<dim3(SL, NH), 256>>>(out + OUT0);

    convw_kernel<<<dim3(DM/32, DM/32),   dim3(32,8)>>>(Wq,  DM,   (size_t)0);
    convw_kernel<<<dim3(2*DM/32, DM/32), dim3(32,8)>>>(Wkv, 2*DM, (size_t)DM*DM);
    convw_kernel<<<dim3(DM/32, DM/32),   dim3(32,8)>>>(Wo,  DM,   (size_t)3*DM*DM);

    conva_kernel<<<BL*DM/4/256, 256>>>(query);

    tgemm_kernel<0><<<dim3(DM/64,   BL/128), 256>>>(nullptr);
    tgemm_kernel<1><<<dim3(2*DM/64, BL/128), 256>>>(nullptr);

    attn_kernel<<<dim3(SL/128, NH, NB), 256>>>();

    tgemm_kernel<2><<<dim3(DM/64,   BL/128), 256>>>(out);
}

// round 11
// speedup vs baseline: 2.4363x; 1.1013x over previous
#include <cuda_runtime.h>
#include <cuda_bf16.h>
#include <cstdint>

#define NH 16
#define SL 2048
#define NB 2
#define HD 64
#define DM 1024
#define BL 4096          // NB*SL
#define NBUCK 32
#define LUTN 4095
#define OUT0 ((size_t)4194304)   // offset of bias region in d_out
#define LOG2E 1.4426950408889634f

__device__ float g_biasrow[NH*LUTN];

// bf16 split buffers
__device__ __nv_bfloat16 g_ah[(size_t)BL*DM];   // activations (query, then attn out)
__device__ __nv_bfloat16 g_al[(size_t)BL*DM];
__device__ __nv_bfloat16 g_wh[(size_t)4*DM*DM]; // Wq^T | Wkv^T | Wo^T, each [N][K]
__device__ __nv_bfloat16 g_wl[(size_t)4*DM*DM];
__device__ __nv_bfloat16 g_qh[(size_t)NB*NH*SL*HD];  // [b,h,q,d], pre-scaled 0.125*log2e
__device__ __nv_bfloat16 g_ql[(size_t)NB*NH*SL*HD];
__device__ __nv_bfloat16 g_kh[(size_t)NB*NH*SL*HD];  // [b,h,key,d]
__device__ __nv_bfloat16 g_kl[(size_t)NB*NH*SL*HD];
__device__ __nv_bfloat16 g_vth[(size_t)NB*NH*HD*SL]; // [b,h,d,key]  (transposed)
__device__ __nv_bfloat16 g_vtl[(size_t)NB*NH*HD*SL];

__device__ __forceinline__ uint32_t smem_to_u32(const void* p){
    uint32_t a; asm("{ .reg .u64 t; cvta.to.shared.u64 t, %1; cvt.u32.u64 %0, t; }" : "=r"(a) : "l"(p));
    return a;
}
__device__ __forceinline__ float ex2(float x){
    float r; asm("ex2.approx.f32 %0, %1;" : "=f"(r) : "f"(x)); return r;
}

// ---------- mma.sync / ldmatrix (base ISA) ----------
__device__ __forceinline__ void ldsm4(uint32_t* r, uint32_t addr){
    asm volatile("ldmatrix.sync.aligned.m8n8.x4.shared.b16 {%0,%1,%2,%3}, [%4];"
        : "=r"(r[0]), "=r"(r[1]), "=r"(r[2]), "=r"(r[3]) : "r"(addr));
}
__device__ __forceinline__ void mma16816(float* d, const uint32_t* a, const uint32_t* b){
    asm volatile(
        "mma.sync.aligned.m16n8k16.row.col.f32.bf16.bf16.f32 "
        "{%0,%1,%2,%3}, {%4,%5,%6,%7}, {%8,%9}, {%0,%1,%2,%3};"
        : "+f"(d[0]), "+f"(d[1]), "+f"(d[2]), "+f"(d[3])
        : "r"(a[0]), "r"(a[1]), "r"(a[2]), "r"(a[3]), "r"(b[0]), "r"(b[1]));
}
// swizzle for 64B rows (4x16B units) — tgemm tiles
__device__ __forceinline__ int swz(int r, int u){
    return r*64 + ((u ^ ((r>>1)&3))<<4);
}
// swizzle for 128B rows (8x16B units) — attention K/V tiles
__device__ __forceinline__ int swzK(int r, int u){
    return r*128 + ((u ^ (r&7))<<4);
}
__device__ __forceinline__ uint32_t pack_bf2(float a, float b){
    __nv_bfloat162 t(__float2bfloat16(a), __float2bfloat16(b));
    return *(uint32_t*)&t;
}

// ---------- bias row LUT ----------
__global__ void biasrow_kernel(const float* __restrict__ rel_bias){
    int idx = blockIdx.x*blockDim.x + threadIdx.x;
    if (idx >= NH*LUTN) return;
    int h = idx / LUTN;
    int d = idx % LUTN - 2047;
    int a = d < 0 ? -d : d;
    int base;
    if (a < 8) base = a;
    else base = 8 + (a>=12) + (a>=16) + (a>=23) + (a>=32) + (a>=46) + (a>=64) + (a>=91);
    int bucket = base + (d > 0 ? 16 : 0);
    g_biasrow[idx] = rel_bias[h*NBUCK + bucket];
}

// ---------- bias output ----------
__global__ void bias_out_kernel(float* __restrict__ out){
    int i = blockIdx.x, h = blockIdx.y;
    const float* br = g_biasrow + h*LUTN + (2047 - i);
    float* dst = out + ((size_t)h*SL + i)*SL;
    for (int j = threadIdx.x*4; j < SL; j += blockDim.x*4){
        float4 w; w.x = br[j]; w.y = br[j+1]; w.z = br[j+2]; w.w = br[j+3];
        *(float4*)(dst + j) = w;
    }
}

// ---------- fp32 query -> bf16 hi/lo split [BL, DM] ----------
__global__ void conva_kernel(const float* __restrict__ in){
    int i = blockIdx.x*blockDim.x + threadIdx.x;   // float4 index
    float4 x = ((const float4*)in)[i];
    __nv_bfloat16 h0 = __float2bfloat16(x.x), h1 = __float2bfloat16(x.y);
    __nv_bfloat16 h2 = __float2bfloat16(x.z), h3 = __float2bfloat16(x.w);
    __nv_bfloat16 l0 = __float2bfloat16(x.x - __bfloat162float(h0));
    __nv_bfloat16 l1 = __float2bfloat16(x.y - __bfloat162float(h1));
    __nv_bfloat16 l2 = __float2bfloat16(x.z - __bfloat162float(h2));
    __nv_bfloat16 l3 = __float2bfloat16(x.w - __bfloat162float(h3));
    __nv_bfloat162* ph2 = (__nv_bfloat162*)g_ah;
    __nv_bfloat162* pl2 = (__nv_bfloat162*)g_al;
    ph2[2*i]   = __nv_bfloat162(h0, h1);
    ph2[2*i+1] = __nv_bfloat162(h2, h3);
    pl2[2*i]   = __nv_bfloat162(l0, l1);
    pl2[2*i+1] = __nv_bfloat162(l2, l3);
}

// ---------- transpose + split weights: W[K=1024][N] -> g_wh/g_wl[obase + n*DM + k] ----------
__global__ void convw_kernel(const float* __restrict__ W, int N, size_t obase){
    __shared__ float tile[32][33];
    int n0 = blockIdx.x*32, k0 = blockIdx.y*32;
    int tx = threadIdx.x;
    for (int r = threadIdx.y; r < 32; r += 8)
        tile[r][tx] = W[(size_t)(k0+r)*N + n0 + tx];
    __syncthreads();
    for (int r = threadIdx.y; r < 32; r += 8){
        float x = tile[tx][r];                 // = W[k0+tx][n0+r]
        __nv_bfloat16 h = __float2bfloat16(x);
        __nv_bfloat16 l = __float2bfloat16(x - __bfloat162float(h));
        size_t o = obase + (size_t)(n0 + r)*DM + k0 + tx;
        g_wh[o] = h; g_wl[o] = l;
    }
}

// ---------- element writer per GEMM mode ----------
template<int MODE>
__device__ __forceinline__ void put_elem(int r, int c, float v, float* out){
    if (MODE == 0){                   // q: scale by 0.125*log2e (base-2 softmax), split, [b,h,q,d]
        int b = r >> 11, l = r & 2047, hh = c >> 6, d = c & 63;
        float x = v * (0.125f * LOG2E);
        __nv_bfloat16 th = __float2bfloat16(x);
        __nv_bfloat16 tl = __float2bfloat16(x - __bfloat162float(th));
        size_t idx = (((size_t)(b*NH + hh))*SL + l)*HD + d;
        g_qh[idx] = th; g_ql[idx] = tl;
    } else if (MODE == 1){            // k: [b,h,key,d] split; v: transposed [b,h,d,key] split
        int b = r >> 11, l = r & 2047;
        __nv_bfloat16 th = __float2bfloat16(v);
        __nv_bfloat16 tl = __float2bfloat16(v - __bfloat162float(th));
        if (c < DM){
            int hh = c >> 6, d = c & 63;
            size_t idx = (((size_t)(b*NH + hh))*SL + l)*HD + d;
            g_kh[idx] = th; g_kl[idx] = tl;
        } else {
            int cc = c - DM; int hh = cc >> 6, d = cc & 63;
            size_t idx = (((size_t)(b*NH + hh))*HD + d)*SL + l;
            g_vth[idx] = th; g_vtl[idx] = tl;
        }
    } else {                          // output projection -> d_out [BL, DM]
        out[(size_t)r*DM + c] = v;
    }
}

// ---------- bf16-split mma.sync GEMM: C[4096, N] = A[4096,1024] @ Wt^T ----------
template<int MODE>
__global__ __launch_bounds__(256)
void tgemm_kernel(float* __restrict__ out){
    __shared__ __align__(128) char smem[49152];
    int tid = threadIdx.x, lane = tid & 31, wid = tid >> 5;
    int wm = wid & 1, wn = wid >> 1;
    int row0 = blockIdx.y * 128, col0 = blockIdx.x * 64;

    const size_t WOFF = (MODE == 0) ? 0 : (MODE == 1) ? (size_t)DM*DM : (size_t)3*DM*DM;
    const __nv_bfloat16* Asrc_h = g_ah + (size_t)row0*DM;
    const __nv_bfloat16* Asrc_l = g_al + (size_t)row0*DM;
    const __nv_bfloat16* Bsrc_h = g_wh + WOFF + (size_t)col0*DM;
    const __nv_bfloat16* Bsrc_l = g_wl + WOFF + (size_t)col0*DM;

    int lr = tid >> 2, lu = tid & 3;   // loader coords: row, 16B-unit

    uint4 v[6];
    auto ldg_chunk = [&](int kc){
        size_t off = (size_t)lr*DM + kc*32 + lu*8;
        v[0] = *(const uint4*)(Asrc_h + off);
        v[1] = *(const uint4*)(Asrc_h + off + (size_t)64*DM);
        v[2] = *(const uint4*)(Asrc_l + off);
        v[3] = *(const uint4*)(Asrc_l + off + (size_t)64*DM);
        v[4] = *(const uint4*)(Bsrc_h + off);
        v[5] = *(const uint4*)(Bsrc_l + off);
    };
    auto sts_chunk = [&](int s){
        char* st = smem + s*24576;
        *(uint4*)(st +         swz(lr,    lu)) = v[0];
        *(uint4*)(st +         swz(lr+64, lu)) = v[1];
        *(uint4*)(st +  8192 + swz(lr,    lu)) = v[2];
        *(uint4*)(st +  8192 + swz(lr+64, lu)) = v[3];
        *(uint4*)(st + 16384 + swz(lr,    lu)) = v[4];
        *(uint4*)(st + 20480 + swz(lr,    lu)) = v[5];
    };

    uint32_t sbase = smem_to_u32(smem);
    int mat = lane >> 3, rim = lane & 7;

    float acc[4][2][4];
    #pragma unroll
    for (int a = 0; a < 4; a++)
        #pragma unroll
        for (int b = 0; b < 2; b++)
            #pragma unroll
            for (int c = 0; c < 4; c++) acc[a][b][c] = 0.f;

    ldg_chunk(0);
    sts_chunk(0);
    __syncthreads();

    #pragma unroll 1
    for (int kc = 0; kc < 32; kc++){
        int s = kc & 1;
        if (kc < 31) ldg_chunk(kc + 1);

        uint32_t sa_h = sbase + s*24576;
        uint32_t sa_l = sa_h + 8192;
        uint32_t sb_h = sa_h + 16384;
        uint32_t sb_l = sa_h + 20480;

        #pragma unroll
        for (int kk = 0; kk < 2; kk++){
            int un = 2*kk + (mat >> 1);
            int br = wn*16 + (mat & 1)*8 + rim;
            uint32_t tb[4], bh[2][2], bl[2][2];
            ldsm4(tb, sb_h + swz(br, un));
            bh[0][0]=tb[0]; bh[0][1]=tb[2]; bh[1][0]=tb[1]; bh[1][1]=tb[3];
            ldsm4(tb, sb_l + swz(br, un));
            bl[0][0]=tb[0]; bl[0][1]=tb[2]; bl[1][0]=tb[1]; bl[1][1]=tb[3];
            #pragma unroll
            for (int mt = 0; mt < 4; mt++){
                int ar = wm*64 + mt*16 + (mat & 1)*8 + rim;
                uint32_t ah[4], al[4];
                ldsm4(ah, sa_h + swz(ar, un));
                ldsm4(al, sa_l + swz(ar, un));
                #pragma unroll
                for (int nf = 0; nf < 2; nf++){
                    mma16816(acc[mt][nf], ah, bh[nf]);
                    mma16816(acc[mt][nf], ah, bl[nf]);
                    mma16816(acc[mt][nf], al, bh[nf]);
                }
            }
        }
        if (kc < 31){
            sts_chunk(s ^ 1);
            __syncthreads();
        }
    }

    #pragma unroll
    for (int mt = 0; mt < 4; mt++)
        #pragma unroll
        for (int nf = 0; nf < 2; nf++){
            int m = row0 + wm*64 + mt*16 + (lane >> 2);
            int c = col0 + wn*16 + nf*8 + 2*(lane & 3);
            put_elem<MODE>(m,     c,     acc[mt][nf][0], out);
            put_elem<MODE>(m,     c + 1, acc[mt][nf][1], out);
            put_elem<MODE>(m + 8, c,     acc[mt][nf][2], out);
            put_elem<MODE>(m + 8, c + 1, acc[mt][nf][3], out);
        }
}

// ---------- flash attention via mma.sync, bf16 3-term split, base-2 softmax ----------
// 8 warps x 16 q-rows = 128 q-rows per CTA. K-tiles of 64 keys. 2 CTAs/SM (128-reg cap).
// SMEM (static 48KB): Kh@0, Kl@8192, Vth@16384, Vtl@24576 (each 64x128B swizzled), bias@32768 (16KB)
__global__ __launch_bounds__(256, 2)
void attn_kernel(){
    __shared__ __align__(128) char smem[49152];
    float* sh_bias = (float*)(smem + 32768);

    int tid = threadIdx.x, lane = tid & 31, wid = tid >> 5;
    int g = lane >> 2, tig = lane & 3, mat = lane >> 3, rim = lane & 7;
    int h = blockIdx.y, b = blockIdx.z;
    size_t bhoff = ((size_t)(b*NH + h))*SL*HD;
    int qrow0 = blockIdx.x*128 + wid*16;
    int r0 = qrow0 + g;                 // thread's first q-row; second is r0+8

    // bias LUT pre-scaled by log2e (base-2 softmax); output bias path uses unscaled g_biasrow
    #pragma unroll 1
    for (int x = tid; x < LUTN; x += 256) sh_bias[x] = g_biasrow[h*LUTN + x] * LOG2E;

    // Q fragments (a-frag layout), loaded once from global
    uint32_t qh[4][4], ql[4][4];
    #pragma unroll
    for (int kc = 0; kc < 4; kc++){
        size_t o00 = bhoff + (size_t)r0*HD     + kc*16 + 2*tig;
        size_t o10 = bhoff + (size_t)(r0+8)*HD + kc*16 + 2*tig;
        qh[kc][0] = *(const uint32_t*)(g_qh + o00);
        qh[kc][1] = *(const uint32_t*)(g_qh + o10);
        qh[kc][2] = *(const uint32_t*)(g_qh + o00 + 8);
        qh[kc][3] = *(const uint32_t*)(g_qh + o10 + 8);
        ql[kc][0] = *(const uint32_t*)(g_ql + o00);
        ql[kc][1] = *(const uint32_t*)(g_ql + o10);
        ql[kc][2] = *(const uint32_t*)(g_ql + o00 + 8);
        ql[kc][3] = *(const uint32_t*)(g_ql + o10 + 8);
    }

    float S[8][4], O[8][4];
    #pragma unroll
    for (int nt = 0; nt < 8; nt++)
        #pragma unroll
        for (int vv = 0; vv < 4; vv++) O[nt][vv] = 0.f;
    float m0 = -1e30f, m1 = -1e30f, l0 = 0.f, l1 = 0.f;

    uint32_t sbase = smem_to_u32(smem);
    uint32_t sKh = sbase, sKl = sbase + 8192, sVh = sbase + 16384, sVl = sbase + 24576;
    int ib0 = 2047 - r0;

    #pragma unroll 1
    for (int kt = 0; kt < 32; kt++){
        int j0 = kt << 6;
        __syncthreads();
        #pragma unroll
        for (int i = 0; i < 2; i++){
            int id = tid + 256*i, r = id >> 3, u = id & 7;
            int so = swzK(r, u);
            *(uint4*)(smem + so)         = *(const uint4*)(g_kh  + bhoff + (size_t)(j0+r)*HD + u*8);
            *(uint4*)(smem + 8192 + so)  = *(const uint4*)(g_kl  + bhoff + (size_t)(j0+r)*HD + u*8);
            *(uint4*)(smem + 16384 + so) = *(const uint4*)(g_vth + bhoff + (size_t)r*SL + j0 + u*8);
            *(uint4*)(smem + 24576 + so) = *(const uint4*)(g_vtl + bhoff + (size_t)r*SL + j0 + u*8);
        }
        __syncthreads();

        // ---- S init = bias (C-init), then S += Q K^T (3-term split) ----
        #pragma unroll
        for (int nt = 0; nt < 8; nt++){
            int j = j0 + nt*8 + 2*tig;
            S[nt][0] = sh_bias[ib0 + j];
            S[nt][1] = sh_bias[ib0 + j + 1];
            S[nt][2] = sh_bias[ib0 - 8 + j];
            S[nt][3] = sh_bias[ib0 - 8 + j + 1];
        }
        #pragma unroll
        for (int kc = 0; kc < 4; kc++){
            #pragma unroll
            for (int np = 0; np < 4; np++){
                int so = swzK(np*16 + (mat & 1)*8 + rim, 2*kc + (mat >> 1));
                uint32_t tb[4], bh0[2], bh1[2], bl0[2], bl1[2];
                ldsm4(tb, sKh + so);
                bh0[0]=tb[0]; bh0[1]=tb[2]; bh1[0]=tb[1]; bh1[1]=tb[3];
                ldsm4(tb, sKl + so);
                bl0[0]=tb[0]; bl0[1]=tb[2]; bl1[0]=tb[1]; bl1[1]=tb[3];
                mma16816(S[2*np],   qh[kc], bh0);
                mma16816(S[2*np],   qh[kc], bl0);
                mma16816(S[2*np],   ql[kc], bh0);
                mma16816(S[2*np+1], qh[kc], bh1);
                mma16816(S[2*np+1], qh[kc], bl1);
                mma16816(S[2*np+1], ql[kc], bh1);
            }
        }

        // ---- online softmax (base 2) ----
        float mx0 = -1e30f, mx1 = -1e30f;
        #pragma unroll
        for (int nt = 0; nt < 8; nt++){
            mx0 = fmaxf(mx0, fmaxf(S[nt][0], S[nt][1]));
            mx1 = fmaxf(mx1, fmaxf(S[nt][2], S[nt][3]));
        }
        mx0 = fmaxf(mx0, __shfl_xor_sync(0xffffffffu, mx0, 1));
        mx0 = fmaxf(mx0, __shfl_xor_sync(0xffffffffu, mx0, 2));
        mx1 = fmaxf(mx1, __shfl_xor_sync(0xffffffffu, mx1, 1));
        mx1 = fmaxf(mx1, __shfl_xor_sync(0xffffffffu, mx1, 2));
        float mn0 = fmaxf(m0, mx0), mn1 = fmaxf(m1, mx1);
        float c0 = ex2(m0 - mn0), c1 = ex2(m1 - mn1);
        float s0 = 0.f, s1 = 0.f;
        #pragma unroll
        for (int nt = 0; nt < 8; nt++){
            S[nt][0] = ex2(S[nt][0] - mn0);
            S[nt][1] = ex2(S[nt][1] - mn0);
            S[nt][2] = ex2(S[nt][2] - mn1);
            S[nt][3] = ex2(S[nt][3] - mn1);
            s0 += S[nt][0] + S[nt][1];
            s1 += S[nt][2] + S[nt][3];
            O[nt][0] *= c0; O[nt][1] *= c0;
            O[nt][2] *= c1; O[nt][3] *= c1;
        }
        s0 += __shfl_xor_sync(0xffffffffu, s0, 1);
        s0 += __shfl_xor_sync(0xffffffffu, s0, 2);
        s1 += __shfl_xor_sync(0xffffffffu, s1, 1);
        s1 += __shfl_xor_sync(0xffffffffu, s1, 2);
        l0 = l0*c0 + s0;  l1 = l1*c1 + s1;
        m0 = mn0;  m1 = mn1;

        // ---- O += P V (3-term split; P a-frags built from S c-frags) ----
        #pragma unroll
        for (int kc2 = 0; kc2 < 4; kc2++){
            int t0 = 2*kc2, t1 = 2*kc2 + 1;
            uint32_t ph[4], pl[4];
            float h00 = __bfloat162float(__float2bfloat16(S[t0][0]));
            float h01 = __bfloat162float(__float2bfloat16(S[t0][1]));
            float h02 = __bfloat162float(__float2bfloat16(S[t0][2]));
            float h03 = __bfloat162float(__float2bfloat16(S[t0][3]));
            float h10 = __bfloat162float(__float2bfloat16(S[t1][0]));
            float h11 = __bfloat162float(__float2bfloat16(S[t1][1]));
            float h12 = __bfloat162float(__float2bfloat16(S[t1][2]));
            float h13 = __bfloat162float(__float2bfloat16(S[t1][3]));
            ph[0] = pack_bf2(h00, h01);
            ph[1] = pack_bf2(h02, h03);
            ph[2] = pack_bf2(h10, h11);
            ph[3] = pack_bf2(h12, h13);
            pl[0] = pack_bf2(S[t0][0] - h00, S[t0][1] - h01);
            pl[1] = pack_bf2(S[t0][2] - h02, S[t0][3] - h03);
            pl[2] = pack_bf2(S[t1][0] - h10, S[t1][1] - h11);
            pl[3] = pack_bf2(S[t1][2] - h12, S[t1][3] - h13);
            #pragma unroll
            for (int np = 0; np < 4; np++){
                int so = swzK(np*16 + (mat & 1)*8 + rim, 2*kc2 + (mat >> 1));
                uint32_t tb[4], vh0[2], vh1[2], vl0[2], vl1[2];
                ldsm4(tb, sVh + so);
                vh0[0]=tb[0]; vh0[1]=tb[2]; vh1[0]=tb[1]; vh1[1]=tb[3];
                ldsm4(tb, sVl + so);
                vl0[0]=tb[0]; vl0[1]=tb[2]; vl1[0]=tb[1]; vl1[1]=tb[3];
                mma16816(O[2*np],   ph, vh0);
                mma16816(O[2*np],   ph, vl0);
                mma16816(O[2*np],   pl, vh0);
                mma16816(O[2*np+1], ph, vh1);
                mma16816(O[2*np+1], ph, vl1);
                mma16816(O[2*np+1], pl, vh1);
            }
        }
    }

    // ---- epilogue: normalize, bf16-split, write g_ah/g_al directly ----
    float rc0 = 1.0f / l0, rc1 = 1.0f / l1;
    size_t rowA = ((size_t)(b*SL + r0))*DM + h*HD;
    size_t rowB = ((size_t)(b*SL + r0 + 8))*DM + h*HD;
    #pragma unroll
    for (int nt = 0; nt < 8; nt++){
        int d = nt*8 + 2*tig;
        float o0 = O[nt][0]*rc0, o1 = O[nt][1]*rc0;
        float o2 = O[nt][2]*rc1, o3 = O[nt][3]*rc1;
        __nv_bfloat16 h0 = __float2bfloat16(o0), h1 = __float2bfloat16(o1);
        __nv_bfloat16 h2 = __float2bfloat16(o2), h3 = __float2bfloat16(o3);
        *(__nv_bfloat162*)(g_ah + rowA + d) = __nv_bfloat162(h0, h1);
        *(__nv_bfloat162*)(g_ah + rowB + d) = __nv_bfloat162(h2, h3);
        *(__nv_bfloat162*)(g_al + rowA + d) = __nv_bfloat162(
            __float2bfloat16(o0 - __bfloat162float(h0)), __float2bfloat16(o1 - __bfloat162float(h1)));
        *(__nv_bfloat162*)(g_al + rowB + d) = __nv_bfloat162(
            __float2bfloat16(o2 - __bfloat162float(h2)), __float2bfloat16(o3 - __bfloat162float(h3)));
    }
}

extern "C" void kernel_launch(void* const* d_in, const int* in_sizes, int n_in,
                              void* d_out, int out_size){
    const float* query    = (const float*)d_in[0];
    const float* Wq       = (const float*)d_in[1];
    const float* Wkv      = (const float*)d_in[2];
    const float* Wo       = (const float*)d_in[3];
    const float* rel_bias = (const float*)d_in[4];
    float* out = (float*)d_out;

    biasrow_kernel<<<(NH*LUTN + 255)/256, 256>>>(rel_bias);
    bias_out_kernel<<<dim3(SL, NH), 256>>>(out + OUT0);

    convw_kernel<<<dim3(DM/32, DM/32),   dim3(32,8)>>>(Wq,  DM,   (size_t)0);
    convw_kernel<<<dim3(2*DM/32, DM/32), dim3(32,8)>>>(Wkv, 2*DM, (size_t)DM*DM);
    convw_kernel<<<dim3(DM/32, DM/32),   dim3(32,8)>>>(Wo,  DM,   (size_t)3*DM*DM);

    conva_kernel<<<BL*DM/4/256, 256>>>(query);

    tgemm_kernel<0><<<dim3(DM/64,   BL/128), 256>>>(nullptr);
    tgemm_kernel<1><<<dim3(2*DM/64, BL/128), 256>>>(nullptr);

    attn_kernel<<<dim3(SL/128, NH, NB), 256>>>();

    tgemm_kernel<2><<<dim3(DM/64,   BL/128), 256>>>(out);
}

// round 12
// speedup vs baseline: 2.4533x; 1.0070x over previous
#include <cuda_runtime.h>
#include <cuda_bf16.h>
#include <cstdint>

#define NH 16
#define SL 2048
#define NB 2
#define HD 64
#define DM 1024
#define BL 4096          // NB*SL
#define NBUCK 32
#define LUTN 4095
#define OUT0 ((size_t)4194304)   // offset of bias region in d_out
#define LOG2E 1.4426950408889634f

__device__ float g_biasrow[NH*LUTN];

// bf16 split buffers
__device__ __nv_bfloat16 g_ah[(size_t)BL*DM];   // activations (query, then attn out)
__device__ __nv_bfloat16 g_al[(size_t)BL*DM];
__device__ __nv_bfloat16 g_wh[(size_t)4*DM*DM]; // Wq^T | Wkv^T | Wo^T, each [N][K]
__device__ __nv_bfloat16 g_wl[(size_t)4*DM*DM];
__device__ __nv_bfloat16 g_qh[(size_t)NB*NH*SL*HD];  // [b,h,q,d], pre-scaled 0.125*log2e
__device__ __nv_bfloat16 g_ql[(size_t)NB*NH*SL*HD];
__device__ __nv_bfloat16 g_kh[(size_t)NB*NH*SL*HD];  // [b,h,key,d]
__device__ __nv_bfloat16 g_kl[(size_t)NB*NH*SL*HD];
__device__ __nv_bfloat16 g_vth[(size_t)NB*NH*HD*SL]; // [b,h,d,key]  (transposed)
__device__ __nv_bfloat16 g_vtl[(size_t)NB*NH*HD*SL];

__device__ __forceinline__ uint32_t smem_to_u32(const void* p){
    uint32_t a; asm("{ .reg .u64 t; cvta.to.shared.u64 t, %1; cvt.u32.u64 %0, t; }" : "=r"(a) : "l"(p));
    return a;
}
__device__ __forceinline__ float ex2(float x){
    float r; asm("ex2.approx.f32 %0, %1;" : "=f"(r) : "f"(x)); return r;
}

// ---------- mma.sync / ldmatrix (base ISA) ----------
__device__ __forceinline__ void ldsm4(uint32_t* r, uint32_t addr){
    asm volatile("ldmatrix.sync.aligned.m8n8.x4.shared.b16 {%0,%1,%2,%3}, [%4];"
        : "=r"(r[0]), "=r"(r[1]), "=r"(r[2]), "=r"(r[3]) : "r"(addr));
}
__device__ __forceinline__ void mma16816(float* d, const uint32_t* a, const uint32_t* b){
    asm volatile(
        "mma.sync.aligned.m16n8k16.row.col.f32.bf16.bf16.f32 "
        "{%0,%1,%2,%3}, {%4,%5,%6,%7}, {%8,%9}, {%0,%1,%2,%3};"
        : "+f"(d[0]), "+f"(d[1]), "+f"(d[2]), "+f"(d[3])
        : "r"(a[0]), "r"(a[1]), "r"(a[2]), "r"(a[3]), "r"(b[0]), "r"(b[1]));
}
// swizzle for 64B rows (4x16B units) — tgemm tiles
__device__ __forceinline__ int swz(int r, int u){
    return r*64 + ((u ^ ((r>>1)&3))<<4);
}
// swizzle for 128B rows (8x16B units) — attention K/V tiles
__device__ __forceinline__ int swzK(int r, int u){
    return r*128 + ((u ^ (r&7))<<4);
}
__device__ __forceinline__ uint32_t pack_bf2(float a, float b){
    __nv_bfloat162 t(__float2bfloat16(a), __float2bfloat16(b));
    return *(uint32_t*)&t;
}

// ---------- bias row LUT ----------
__global__ void biasrow_kernel(const float* __restrict__ rel_bias){
    int idx = blockIdx.x*blockDim.x + threadIdx.x;
    if (idx >= NH*LUTN) return;
    int h = idx / LUTN;
    int d = idx % LUTN - 2047;
    int a = d < 0 ? -d : d;
    int base;
    if (a < 8) base = a;
    else base = 8 + (a>=12) + (a>=16) + (a>=23) + (a>=32) + (a>=46) + (a>=64) + (a>=91);
    int bucket = base + (d > 0 ? 16 : 0);
    g_biasrow[idx] = rel_bias[h*NBUCK + bucket];
}

// ---------- fp32 query -> bf16 hi/lo split [BL, DM] ----------
__global__ void conva_kernel(const float* __restrict__ in){
    int i = blockIdx.x*blockDim.x + threadIdx.x;   // float4 index
    float4 x = ((const float4*)in)[i];
    __nv_bfloat16 h0 = __float2bfloat16(x.x), h1 = __float2bfloat16(x.y);
    __nv_bfloat16 h2 = __float2bfloat16(x.z), h3 = __float2bfloat16(x.w);
    __nv_bfloat16 l0 = __float2bfloat16(x.x - __bfloat162float(h0));
    __nv_bfloat16 l1 = __float2bfloat16(x.y - __bfloat162float(h1));
    __nv_bfloat16 l2 = __float2bfloat16(x.z - __bfloat162float(h2));
    __nv_bfloat16 l3 = __float2bfloat16(x.w - __bfloat162float(h3));
    __nv_bfloat162* ph2 = (__nv_bfloat162*)g_ah;
    __nv_bfloat162* pl2 = (__nv_bfloat162*)g_al;
    ph2[2*i]   = __nv_bfloat162(h0, h1);
    ph2[2*i+1] = __nv_bfloat162(h2, h3);
    pl2[2*i]   = __nv_bfloat162(l0, l1);
    pl2[2*i+1] = __nv_bfloat162(l2, l3);
}

// ---------- transpose + split weights: W[K=1024][N] -> g_wh/g_wl[obase + n*DM + k] ----------
__global__ void convw_kernel(const float* __restrict__ W, int N, size_t obase){
    __shared__ float tile[32][33];
    int n0 = blockIdx.x*32, k0 = blockIdx.y*32;
    int tx = threadIdx.x;
    for (int r = threadIdx.y; r < 32; r += 8)
        tile[r][tx] = W[(size_t)(k0+r)*N + n0 + tx];
    __syncthreads();
    for (int r = threadIdx.y; r < 32; r += 8){
        float x = tile[tx][r];                 // = W[k0+tx][n0+r]
        __nv_bfloat16 h = __float2bfloat16(x);
        __nv_bfloat16 l = __float2bfloat16(x - __bfloat162float(h));
        size_t o = obase + (size_t)(n0 + r)*DM + k0 + tx;
        g_wh[o] = h; g_wl[o] = l;
    }
}

// ---------- element writer per GEMM mode ----------
template<int MODE>
__device__ __forceinline__ void put_elem(int r, int c, float v, float* out){
    if (MODE == 0){                   // q: scale by 0.125*log2e (base-2 softmax), split, [b,h,q,d]
        int b = r >> 11, l = r & 2047, hh = c >> 6, d = c & 63;
        float x = v * (0.125f * LOG2E);
        __nv_bfloat16 th = __float2bfloat16(x);
        __nv_bfloat16 tl = __float2bfloat16(x - __bfloat162float(th));
        size_t idx = (((size_t)(b*NH + hh))*SL + l)*HD + d;
        g_qh[idx] = th; g_ql[idx] = tl;
    } else if (MODE == 1){            // k: [b,h,key,d] split; v: transposed [b,h,d,key] split
        int b = r >> 11, l = r & 2047;
        __nv_bfloat16 th = __float2bfloat16(v);
        __nv_bfloat16 tl = __float2bfloat16(v - __bfloat162float(th));
        if (c < DM){
            int hh = c >> 6, d = c & 63;
            size_t idx = (((size_t)(b*NH + hh))*SL + l)*HD + d;
            g_kh[idx] = th; g_kl[idx] = tl;
        } else {
            int cc = c - DM; int hh = cc >> 6, d = cc & 63;
            size_t idx = (((size_t)(b*NH + hh))*HD + d)*SL + l;
            g_vth[idx] = th; g_vtl[idx] = tl;
        }
    } else {                          // output projection -> d_out [BL, DM]
        out[(size_t)r*DM + c] = v;
    }
}

// ---------- bf16-split mma.sync GEMM: C[4096, N] = A[4096,1024] @ Wt^T ----------
// MODE==1 additionally streams the bias output tensor (one row per k-iter per CTA),
// fusing the old bias_out kernel's 268MB of writes behind the GEMM's MMA waits.
template<int MODE>
__global__ __launch_bounds__(256, 2)
void tgemm_kernel(float* __restrict__ out){
    __shared__ __align__(128) char smem[49152];
    int tid = threadIdx.x, lane = tid & 31, wid = tid >> 5;
    int wm = wid & 1, wn = wid >> 1;
    int row0 = blockIdx.y * 128, col0 = blockIdx.x * 64;

    const size_t WOFF = (MODE == 0) ? 0 : (MODE == 1) ? (size_t)DM*DM : (size_t)3*DM*DM;
    const __nv_bfloat16* Asrc_h = g_ah + (size_t)row0*DM;
    const __nv_bfloat16* Asrc_l = g_al + (size_t)row0*DM;
    const __nv_bfloat16* Bsrc_h = g_wh + WOFF + (size_t)col0*DM;
    const __nv_bfloat16* Bsrc_l = g_wl + WOFF + (size_t)col0*DM;

    int lr = tid >> 2, lu = tid & 3;   // loader coords: row, 16B-unit

    uint4 v[6];
    auto ldg_chunk = [&](int kc){
        size_t off = (size_t)lr*DM + kc*32 + lu*8;
        v[0] = *(const uint4*)(Asrc_h + off);
        v[1] = *(const uint4*)(Asrc_h + off + (size_t)64*DM);
        v[2] = *(const uint4*)(Asrc_l + off);
        v[3] = *(const uint4*)(Asrc_l + off + (size_t)64*DM);
        v[4] = *(const uint4*)(Bsrc_h + off);
        v[5] = *(const uint4*)(Bsrc_l + off);
    };
    auto sts_chunk = [&](int s){
        char* st = smem + s*24576;
        *(uint4*)(st +         swz(lr,    lu)) = v[0];
        *(uint4*)(st +         swz(lr+64, lu)) = v[1];
        *(uint4*)(st +  8192 + swz(lr,    lu)) = v[2];
        *(uint4*)(st +  8192 + swz(lr+64, lu)) = v[3];
        *(uint4*)(st + 16384 + swz(lr,    lu)) = v[4];
        *(uint4*)(st + 20480 + swz(lr,    lu)) = v[5];
    };

    uint32_t sbase = smem_to_u32(smem);
    int mat = lane >> 3, rim = lane & 7;

    float acc[4][2][4];
    #pragma unroll
    for (int a = 0; a < 4; a++)
        #pragma unroll
        for (int b = 0; b < 2; b++)
            #pragma unroll
            for (int c = 0; c < 4; c++) acc[a][b][c] = 0.f;

    ldg_chunk(0);
    sts_chunk(0);
    __syncthreads();

    #pragma unroll 1
    for (int kc = 0; kc < 32; kc++){
        int s = kc & 1;
        if (kc < 31) ldg_chunk(kc + 1);

        uint32_t sa_h = sbase + s*24576;
        uint32_t sa_l = sa_h + 8192;
        uint32_t sb_h = sa_h + 16384;
        uint32_t sb_l = sa_h + 20480;

        #pragma unroll
        for (int kk = 0; kk < 2; kk++){
            int un = 2*kk + (mat >> 1);
            int br = wn*16 + (mat & 1)*8 + rim;
            uint32_t tb[4], bh[2][2], bl[2][2];
            ldsm4(tb, sb_h + swz(br, un));
            bh[0][0]=tb[0]; bh[0][1]=tb[2]; bh[1][0]=tb[1]; bh[1][1]=tb[3];
            ldsm4(tb, sb_l + swz(br, un));
            bl[0][0]=tb[0]; bl[0][1]=tb[2]; bl[1][0]=tb[1]; bl[1][1]=tb[3];
            #pragma unroll
            for (int mt = 0; mt < 4; mt++){
                int ar = wm*64 + mt*16 + (mat & 1)*8 + rim;
                uint32_t ah[4], al[4];
                ldsm4(ah, sa_h + swz(ar, un));
                ldsm4(al, sa_l + swz(ar, un));
                #pragma unroll
                for (int nf = 0; nf < 2; nf++){
                    mma16816(acc[mt][nf], ah, bh[nf]);
                    mma16816(acc[mt][nf], ah, bl[nf]);
                    mma16816(acc[mt][nf], al, bh[nf]);
                }
            }
        }

        // fused bias-output streaming (MODE 1 only): 1024 CTAs x 32 rows = 16x2048 rows
        if (MODE == 1){
            int brow = ((int)(blockIdx.y*gridDim.x + blockIdx.x))*32 + kc;
            int hh = brow >> 11, ii = brow & 2047;
            const float* src = g_biasrow + hh*LUTN + (2047 - ii) + tid*8;
            float4 w0, w1;
            w0.x = src[0]; w0.y = src[1]; w0.z = src[2]; w0.w = src[3];
            w1.x = src[4]; w1.y = src[5]; w1.z = src[6]; w1.w = src[7];
            float4* dst = (float4*)(out + OUT0 + (size_t)brow*SL) + tid*2;
            dst[0] = w0; dst[1] = w1;
        }

        if (kc < 31){
            sts_chunk(s ^ 1);
            __syncthreads();
        }
    }

    #pragma unroll
    for (int mt = 0; mt < 4; mt++)
        #pragma unroll
        for (int nf = 0; nf < 2; nf++){
            int m = row0 + wm*64 + mt*16 + (lane >> 2);
            int c = col0 + wn*16 + nf*8 + 2*(lane & 3);
            put_elem<MODE>(m,     c,     acc[mt][nf][0], out);
            put_elem<MODE>(m,     c + 1, acc[mt][nf][1], out);
            put_elem<MODE>(m + 8, c,     acc[mt][nf][2], out);
            put_elem<MODE>(m + 8, c + 1, acc[mt][nf][3], out);
        }
}

// ---------- flash attention via mma.sync, bf16 3-term split, base-2 softmax ----------
// 8 warps x 16 q-rows = 128 q-rows per CTA. K-tiles of 64 keys. 2 CTAs/SM (128-reg cap).
// SMEM (static 48KB): Kh@0, Kl@8192, Vth@16384, Vtl@24576 (each 64x128B swizzled), bias@32768 (16KB)
__global__ __launch_bounds__(256, 2)
void attn_kernel(){
    __shared__ __align__(128) char smem[49152];
    float* sh_bias = (float*)(smem + 32768);

    int tid = threadIdx.x, lane = tid & 31, wid = tid >> 5;
    int g = lane >> 2, tig = lane & 3, mat = lane >> 3, rim = lane & 7;
    int h = blockIdx.y, b = blockIdx.z;
    size_t bhoff = ((size_t)(b*NH + h))*SL*HD;
    int qrow0 = blockIdx.x*128 + wid*16;
    int r0 = qrow0 + g;                 // thread's first q-row; second is r0+8

    // bias LUT pre-scaled by log2e (base-2 softmax)
    #pragma unroll 1
    for (int x = tid; x < LUTN; x += 256) sh_bias[x] = g_biasrow[h*LUTN + x] * LOG2E;

    // Q fragments (a-frag layout), loaded once from global
    uint32_t qh[4][4], ql[4][4];
    #pragma unroll
    for (int kc = 0; kc < 4; kc++){
        size_t o00 = bhoff + (size_t)r0*HD     + kc*16 + 2*tig;
        size_t o10 = bhoff + (size_t)(r0+8)*HD + kc*16 + 2*tig;
        qh[kc][0] = *(const uint32_t*)(g_qh + o00);
        qh[kc][1] = *(const uint32_t*)(g_qh + o10);
        qh[kc][2] = *(const uint32_t*)(g_qh + o00 + 8);
        qh[kc][3] = *(const uint32_t*)(g_qh + o10 + 8);
        ql[kc][0] = *(const uint32_t*)(g_ql + o00);
        ql[kc][1] = *(const uint32_t*)(g_ql + o10);
        ql[kc][2] = *(const uint32_t*)(g_ql + o00 + 8);
        ql[kc][3] = *(const uint32_t*)(g_ql + o10 + 8);
    }

    float S[8][4], O[8][4];
    #pragma unroll
    for (int nt = 0; nt < 8; nt++)
        #pragma unroll
        for (int vv = 0; vv < 4; vv++) O[nt][vv] = 0.f;
    float m0 = -1e30f, m1 = -1e30f, l0 = 0.f, l1 = 0.f;

    uint32_t sbase = smem_to_u32(smem);
    uint32_t sKh = sbase, sKl = sbase + 8192, sVh = sbase + 16384, sVl = sbase + 24576;
    int ib0 = 2047 - r0;

    #pragma unroll 1
    for (int kt = 0; kt < 32; kt++){
        int j0 = kt << 6;
        __syncthreads();
        #pragma unroll
        for (int i = 0; i < 2; i++){
            int id = tid + 256*i, r = id >> 3, u = id & 7;
            int so = swzK(r, u);
            *(uint4*)(smem + so)         = *(const uint4*)(g_kh  + bhoff + (size_t)(j0+r)*HD + u*8);
            *(uint4*)(smem + 8192 + so)  = *(const uint4*)(g_kl  + bhoff + (size_t)(j0+r)*HD + u*8);
            *(uint4*)(smem + 16384 + so) = *(const uint4*)(g_vth + bhoff + (size_t)r*SL + j0 + u*8);
            *(uint4*)(smem + 24576 + so) = *(const uint4*)(g_vtl + bhoff + (size_t)r*SL + j0 + u*8);
        }
        __syncthreads();

        // ---- S init = bias (C-init), then S += Q K^T (3-term split) ----
        #pragma unroll
        for (int nt = 0; nt < 8; nt++){
            int j = j0 + nt*8 + 2*tig;
            S[nt][0] = sh_bias[ib0 + j];
            S[nt][1] = sh_bias[ib0 + j + 1];
            S[nt][2] = sh_bias[ib0 - 8 + j];
            S[nt][3] = sh_bias[ib0 - 8 + j + 1];
        }
        #pragma unroll
        for (int kc = 0; kc < 4; kc++){
            #pragma unroll
            for (int np = 0; np < 4; np++){
                int so = swzK(np*16 + (mat & 1)*8 + rim, 2*kc + (mat >> 1));
                uint32_t tb[4], bh0[2], bh1[2], bl0[2], bl1[2];
                ldsm4(tb, sKh + so);
                bh0[0]=tb[0]; bh0[1]=tb[2]; bh1[0]=tb[1]; bh1[1]=tb[3];
                ldsm4(tb, sKl + so);
                bl0[0]=tb[0]; bl0[1]=tb[2]; bl1[0]=tb[1]; bl1[1]=tb[3];
                mma16816(S[2*np],   qh[kc], bh0);
                mma16816(S[2*np],   qh[kc], bl0);
                mma16816(S[2*np],   ql[kc], bh0);
                mma16816(S[2*np+1], qh[kc], bh1);
                mma16816(S[2*np+1], qh[kc], bl1);
                mma16816(S[2*np+1], ql[kc], bh1);
            }
        }

        // ---- online softmax (base 2) ----
        float mx0 = -1e30f, mx1 = -1e30f;
        #pragma unroll
        for (int nt = 0; nt < 8; nt++){
            mx0 = fmaxf(mx0, fmaxf(S[nt][0], S[nt][1]));
            mx1 = fmaxf(mx1, fmaxf(S[nt][2], S[nt][3]));
        }
        mx0 = fmaxf(mx0, __shfl_xor_sync(0xffffffffu, mx0, 1));
        mx0 = fmaxf(mx0, __shfl_xor_sync(0xffffffffu, mx0, 2));
        mx1 = fmaxf(mx1, __shfl_xor_sync(0xffffffffu, mx1, 1));
        mx1 = fmaxf(mx1, __shfl_xor_sync(0xffffffffu, mx1, 2));
        float mn0 = fmaxf(m0, mx0), mn1 = fmaxf(m1, mx1);
        float c0 = ex2(m0 - mn0), c1 = ex2(m1 - mn1);
        float s0 = 0.f, s1 = 0.f;
        #pragma unroll
        for (int nt = 0; nt < 8; nt++){
            S[nt][0] = ex2(S[nt][0] - mn0);
            S[nt][1] = ex2(S[nt][1] - mn0);
            S[nt][2] = ex2(S[nt][2] - mn1);
            S[nt][3] = ex2(S[nt][3] - mn1);
            s0 += S[nt][0] + S[nt][1];
            s1 += S[nt][2] + S[nt][3];
            O[nt][0] *= c0; O[nt][1] *= c0;
            O[nt][2] *= c1; O[nt][3] *= c1;
        }
        s0 += __shfl_xor_sync(0xffffffffu, s0, 1);
        s0 += __shfl_xor_sync(0xffffffffu, s0, 2);
        s1 += __shfl_xor_sync(0xffffffffu, s1, 1);
        s1 += __shfl_xor_sync(0xffffffffu, s1, 2);
        l0 = l0*c0 + s0;  l1 = l1*c1 + s1;
        m0 = mn0;  m1 = mn1;

        // ---- O += P V (3-term split; P a-frags built from S c-frags) ----
        #pragma unroll
        for (int kc2 = 0; kc2 < 4; kc2++){
            int t0 = 2*kc2, t1 = 2*kc2 + 1;
            uint32_t ph[4], pl[4];
            float h00 = __bfloat162float(__float2bfloat16(S[t0][0]));
            float h01 = __bfloat162float(__float2bfloat16(S[t0][1]));
            float h02 = __bfloat162float(__float2bfloat16(S[t0][2]));
            float h03 = __bfloat162float(__float2bfloat16(S[t0][3]));
            float h10 = __bfloat162float(__float2bfloat16(S[t1][0]));
            float h11 = __bfloat162float(__float2bfloat16(S[t1][1]));
            float h12 = __bfloat162float(__float2bfloat16(S[t1][2]));
            float h13 = __bfloat162float(__float2bfloat16(S[t1][3]));
            ph[0] = pack_bf2(h00, h01);
            ph[1] = pack_bf2(h02, h03);
            ph[2] = pack_bf2(h10, h11);
            ph[3] = pack_bf2(h12, h13);
            pl[0] = pack_bf2(S[t0][0] - h00, S[t0][1] - h01);
            pl[1] = pack_bf2(S[t0][2] - h02, S[t0][3] - h03);
            pl[2] = pack_bf2(S[t1][0] - h10, S[t1][1] - h11);
            pl[3] = pack_bf2(S[t1][2] - h12, S[t1][3] - h13);
            #pragma unroll
            for (int np = 0; np < 4; np++){
                int so = swzK(np*16 + (mat & 1)*8 + rim, 2*kc2 + (mat >> 1));
                uint32_t tb[4], vh0[2], vh1[2], vl0[2], vl1[2];
                ldsm4(tb, sVh + so);
                vh0[0]=tb[0]; vh0[1]=tb[2]; vh1[0]=tb[1]; vh1[1]=tb[3];
                ldsm4(tb, sVl + so);
                vl0[0]=tb[0]; vl0[1]=tb[2]; vl1[0]=tb[1]; vl1[1]=tb[3];
                mma16816(O[2*np],   ph, vh0);
                mma16816(O[2*np],   ph, vl0);
                mma16816(O[2*np],   pl, vh0);
                mma16816(O[2*np+1], ph, vh1);
                mma16816(O[2*np+1], ph, vl1);
                mma16816(O[2*np+1], pl, vh1);
            }
        }
    }

    // ---- epilogue: normalize, bf16-split, write g_ah/g_al directly ----
    float rc0 = 1.0f / l0, rc1 = 1.0f / l1;
    size_t rowA = ((size_t)(b*SL + r0))*DM + h*HD;
    size_t rowB = ((size_t)(b*SL + r0 + 8))*DM + h*HD;
    #pragma unroll
    for (int nt = 0; nt < 8; nt++){
        int d = nt*8 + 2*tig;
        float o0 = O[nt][0]*rc0, o1 = O[nt][1]*rc0;
        float o2 = O[nt][2]*rc1, o3 = O[nt][3]*rc1;
        __nv_bfloat16 h0 = __float2bfloat16(o0), h1 = __float2bfloat16(o1);
        __nv_bfloat16 h2 = __float2bfloat16(o2), h3 = __float2bfloat16(o3);
        *(__nv_bfloat162*)(g_ah + rowA + d) = __nv_bfloat162(h0, h1);
        *(__nv_bfloat162*)(g_ah + rowB + d) = __nv_bfloat162(h2, h3);
        *(__nv_bfloat162*)(g_al + rowA + d) = __nv_bfloat162(
            __float2bfloat16(o0 - __bfloat162float(h0)), __float2bfloat16(o1 - __bfloat162float(h1)));
        *(__nv_bfloat162*)(g_al + rowB + d) = __nv_bfloat162(
            __float2bfloat16(o2 - __bfloat162float(h2)), __float2bfloat16(o3 - __bfloat162float(h3)));
    }
}

extern "C" void kernel_launch(void* const* d_in, const int* in_sizes, int n_in,
                              void* d_out, int out_size){
    const float* query    = (const float*)d_in[0];
    const float* Wq       = (const float*)d_in[1];
    const float* Wkv      = (const float*)d_in[2];
    const float* Wo       = (const float*)d_in[3];
    const float* rel_bias = (const float*)d_in[4];
    float* out = (float*)d_out;

    biasrow_kernel<<<(NH*LUTN + 255)/256, 256>>>(rel_bias);

    convw_kernel<<<dim3(DM/32, DM/32),   dim3(32,8)>>>(Wq,  DM,   (size_t)0);
    convw_kernel<<<dim3(2*DM/32, DM/32), dim3(32,8)>>>(Wkv, 2*DM, (size_t)DM*DM);
    convw_kernel<<<dim3(DM/32, DM/32),   dim3(32,8)>>>(Wo,  DM,   (size_t)3*DM*DM);

    conva_kernel<<<BL*DM/4/256, 256>>>(query);

    tgemm_kernel<0><<<dim3(DM/64,   BL/128), 256>>>(nullptr);
    tgemm_kernel<1><<<dim3(2*DM/64, BL/128), 256>>>(out);   // also streams bias region

    attn_kernel<<<dim3(SL/128, NH, NB), 256>>>();

    tgemm_kernel<2><<<dim3(DM/64,   BL/128), 256>>>(out);
}